// round 8
// baseline (speedup 1.0000x reference)
#include <cuda_runtime.h>
#include <math.h>

// ---------------- problem constants ----------------
#define BB    4
#define TT    200
#define HOP   120
#define NN    24000          // T*HOP
#define M1    40
#define A1    5
#define HID   256
#define COND  192
#define NCH   8              // 2B channels (0..3 periodic, 4..7 aperiodic)

#define ALPHA 0.466f
#define AAC   0.782844f      // 1 - ALPHA^2
#define P1C   0.4999273f
#define P2C   0.1067005f
#define P3C   0.00956526f
#define P4C   0.0003041358f
#define SRF   24000.0f

// ---------------- scratch (no allocations allowed) ----------------
__device__ float g_bcoef[NCH * TT * M1];   // MLSA coefficients per channel/frame
__device__ float g_eb0[NCH * TT];          // exp(b[0]) per channel/frame
__device__ float g_b1[NCH * TT];           // b[1] per channel/frame
__device__ float g_f0[BB * TT];            // denormed f0 per batch/frame
__device__ float g_exc[BB * NN];           // periodic excitation (0.5 * pulse)
__device__ float g_wav[NCH * NN];          // per-channel filtered waveform
// tree-scan levels: 24000,12000,6000,3000,1500,750,375,187,93,46,23,11,5,2,1
#define SCAN_TOTAL 47993
__device__ float g_scanbuf[BB * SCAN_TOTAL];

// q_k = AAC * (-ALPHA)^k  (hi-half next-sample c correction weights)
#define Q0   0.782844f
#define Q1  -0.3648053f
#define Q2   0.16999927f
#define Q3  -0.07921966f
#define Q4   0.03691636f
#define Q5  -0.01720302f
#define Q6   0.00801661f
#define Q7  -0.00373574f
#define Q8   0.00174086f
#define Q9  -0.00081124f
#define Q10  0.000378038f
#define Q11 -0.000176166f
#define Q12  0.0000820934f
#define Q13 -0.0000382555f
#define Q14  0.0000178271f
#define Q15 -0.00000830743f
#define Q16  0.00000387126f
#define Q17 -0.00000180401f
#define Q18  0.000000840669f

// ==================================================================
// K1: dense frontend: feature embed -> cond -> mel-cepstra -> mc2b
// ==================================================================
__global__ __launch_bounds__(256) void k_frontend(
    const float* __restrict__ mceps, const float* __restrict__ apdcs,
    const float* __restrict__ f0s,
    const float* __restrict__ Wm,  const float* __restrict__ bm,
    const float* __restrict__ Wa,  const float* __restrict__ ba,
    const float* __restrict__ Wf,  const float* __restrict__ bf,
    const float* __restrict__ Wpa, const float* __restrict__ bpa,
    const float* __restrict__ Wpp, const float* __restrict__ bpp,
    const float* __restrict__ Wrp, const float* __restrict__ brp,
    const float* __restrict__ Wra, const float* __restrict__ bra,
    const float* __restrict__ Wap)
{
    int bt = blockIdx.x;            // 0..799
    int b  = bt / TT;
    int t  = bt % TT;
    int tid = threadIdx.x;

    __shared__ float feat[48];      // mcep[40] | apdc[5] | f0
    __shared__ float hsm[HID];
    __shared__ float cam[COND], cpm[COND];
    __shared__ float mcp[M1], mca[M1];

    if (tid < M1)            feat[tid] = mceps[bt * M1 + tid];
    else if (tid < M1 + A1)  feat[tid] = apdcs[bt * A1 + (tid - M1)];
    else if (tid == 45)      feat[45]  = f0s[bt];
    __syncthreads();

    {
        float s = bm[tid] + ba[tid] + bf[tid];
        #pragma unroll 8
        for (int i = 0; i < M1; i++) s = fmaf(feat[i], Wm[i * HID + tid], s);
        #pragma unroll
        for (int i = 0; i < A1; i++) s = fmaf(feat[M1 + i], Wa[i * HID + tid], s);
        s = fmaf(feat[45], Wf[tid], s);
        hsm[tid] = s;
    }
    __syncthreads();

    if (tid < COND) {
        float sa = bpa[tid], sp = bpp[tid];
        #pragma unroll 8
        for (int i = 0; i < HID; i++) {
            float h = hsm[i];
            sa = fmaf(h, Wpa[i * COND + tid], sa);
            sp = fmaf(h, Wpp[i * COND + tid], sp);
        }
        cam[tid] = sa;
        cpm[tid] = sp;
    }
    __syncthreads();

    if (tid < M1) {
        float rp = brp[tid], ra = bra[tid];
        #pragma unroll 8
        for (int i = 0; i < COND; i++) {
            rp = fmaf(cpm[i], Wrp[i * M1 + tid], rp);
            ra = fmaf(cam[i], Wra[i * M1 + tid], ra);
        }
        float apm = 0.f;
        #pragma unroll
        for (int i = 0; i < A1; i++) apm = fmaf(feat[M1 + i], Wap[i * M1 + tid], apm);
        float sp = feat[tid];
        mcp[tid] = sp + 0.1f * tanhf(rp);
        mca[tid] = sp + 0.1f * tanhf(ra) + apm;
    }
    __syncthreads();

    if (tid < 2) {
        const float* mc = (tid == 0) ? mcp : mca;
        int ch = (tid == 0) ? b : (4 + b);
        float* dst = g_bcoef + (ch * TT + t) * M1;
        float bbv = 0.f, b1v = 0.f;
        #pragma unroll
        for (int m = M1 - 1; m >= 0; m--) {
            bbv = fmaf(-ALPHA, bbv, mc[m]);
            dst[m] = bbv;
            if (m == 1) b1v = bbv;
        }
        g_eb0[ch * TT + t] = expf(bbv);
        g_b1[ch * TT + t]  = b1v;
        if (tid == 0) g_f0[b * TT + t] = expf(fmaf(feat[45], 0.25f, 5.0f));
    }
}

// ==================================================================
// K2: pulse excitation — bit-exact replication of JAX associative_scan
// ==================================================================
__global__ __launch_bounds__(256) void k_pulse()
{
    const int b   = blockIdx.x;
    const int tid = threadIdx.x;
    const int NTH = blockDim.x;

    const int ln[15] = {24000,12000,6000,3000,1500,750,375,187,93,46,23,11,5,2,1};
    int off[15];
    off[0] = 0;
    #pragma unroll
    for (int k = 1; k < 15; k++) off[k] = off[k-1] + ln[k-1];

    float* buf = g_scanbuf + b * SCAN_TOTAL;

    for (int i = tid; i < NN; i += NTH)
        buf[i] = g_f0[b * TT + i / HOP] / SRF;
    __syncthreads();

    for (int k = 0; k < 14; k++) {
        const float* src = buf + off[k];
        float*       dst = buf + off[k+1];
        const int nn1 = ln[k+1];
        for (int i = tid; i < nn1; i += NTH)
            dst[i] = src[2*i] + src[2*i+1];
        __syncthreads();
    }

    for (int k = 13; k >= 0; k--) {
        float*       a = buf + off[k];
        const float* s = buf + off[k+1];
        const int n = ln[k];
        for (int i = tid; i < n; i += NTH) {
            float v;
            if (i & 1)            v = s[i >> 1];
            else if (i == 0)      v = a[0];
            else                  v = s[(i >> 1) - 1] + a[i];
            a[i] = v;
        }
        __syncthreads();
    }

    for (int i = tid; i < NN; i += NTH) {
        float w  = floorf(buf[i]);
        float wp = (i == 0) ? 0.f : floorf(buf[i-1]);
        float f  = g_f0[b * TT + i / HOP];
        float amp = 0.5f * sqrtf(SRF / fmaxf(f, 1.0f));
        g_exc[b * NN + i] = (w > wp) ? amp : 0.f;
    }
}

// ==================================================================
// K3: MLSA synthesis filter scan — ONE WARP PER CHANNEL.
// 38-order chain split into exact 2-segment superposition:
//   lanes 0..3 : LO half (orders 0..18) of tap = lane, exact seed from d1
//   lanes 4..7 : HI half (orders 19..37) of tap = lane-4, zero-seeded A[];
//                exactness restored by q_k*e_prev fold into c, and cb*e fold
//                into y (applied on the LO lane which owns e = new_18).
// Chain 19x4=76 cyc; single 8-wide shfl gather per sample; no smem barriers.
// ==================================================================
__global__ __launch_bounds__(32, 1) void k_mlsa(const float* __restrict__ noise)
{
    const int c    = blockIdx.x;          // channel
    const int lane = threadIdx.x;
    const bool lo  = (lane < 4);

    __shared__ float sm_exc[HOP];

    // per-lane correction weights: q_k = AAC*(-a)^k on HI lanes, 0 on LO
    float q[19];
    {
        const float QT[19] = {Q0,Q1,Q2,Q3,Q4,Q5,Q6,Q7,Q8,Q9,Q10,Q11,Q12,Q13,Q14,Q15,Q16,Q17,Q18};
        #pragma unroll
        for (int k = 0; k < 19; k++) q[k] = lo ? 0.f : QT[k];
    }

    // ---- stage-2 half-state ----
    float n[19];
    #pragma unroll
    for (int k = 0; k < 19; k++) n[k] = 0.f;
    float breg[19];
    float d1o = 0.f, xin = 0.f, eprev = 0.f;

    // ---- stage-1 state (replicated on every lane) ----
    float x1p = 0.f, npt0 = 0.f, npt1 = 0.f, npt2 = 0.f;
    float na0 = 0.f, na1 = 0.f, na2 = 0.f, na3 = 0.f;

    const float* bc  = g_bcoef + c * TT * M1;
    const bool periodic = (c < 4);
    const float* srcf = periodic ? (g_exc + c * NN) : (noise + (c - 4) * NN);
    const float scl   = periodic ? 1.0f : 0.5f;
    float* wout = g_wav + c * NN;

    const int boff = lo ? 2 : 21;         // b indices for this half

    for (int fr = 0; fr < TT; fr++) {
        const float* bf_ = bc + fr * M1;
        const float eb0 = g_eb0[c * TT + fr];
        const float b1  = g_b1[c * TT + fr];
        #pragma unroll
        for (int k = 0; k < 19; k++) breg[k] = bf_[boff + k];

        // per-frame y-correction scalar: cb = sum b[21+k]*(-a)^(k+1) (Horner)
        float hh = 0.f;
        #pragma unroll
        for (int k = 18; k >= 0; k--) hh = fmaf(-ALPHA, hh, bf_[21 + k]);
        const float cb = lo ? (-ALPHA * hh) : 0.f;

        // stage excitation tile for this frame into smem (float4 loads)
        __syncwarp();
        if (lane < 30) {
            float4 v = *reinterpret_cast<const float4*>(srcf + fr * HOP + lane * 4);
            float4 w;
            w.x = v.x * scl; w.y = v.y * scl; w.z = v.z * scl; w.w = v.w * scl;
            reinterpret_cast<float4*>(sm_exc)[lane] = w;
        }
        __syncwarp();

        float excv = sm_exc[0];
        const int base = fr * HOP;

        for (int j = 0; j < HOP; j++) {
            const int i = base + j;

            // ---- stage-1 (mlsadf1), replicated ----
            float x  = excv * eb0;
            float m0 = fmaf(ALPHA, na0, AAC * x1p);
            float m1 = fmaf(ALPHA, na1, AAC * npt0);
            float m2 = fmaf(ALPHA, na2, AAC * npt1);
            float m3 = fmaf(ALPHA, na3, AAC * npt2);
            na0 = m0; na1 = m1; na2 = m2; na3 = m3;
            float p0 = m0 * b1, p1 = m1 * b1, p2 = m2 * b1, p3 = m3 * b1;
            float sA1 = fmaf(P3C, p2, P1C * p0);
            float sB1 = fmaf(P4C, p3, P2C * p1);
            float x1 = x + (sA1 - sB1);
            float y1 = x1 + (sA1 + sB1);
            x1p = x1; npt0 = p0; npt1 = p1; npt2 = p2;
            if (j < HOP - 1) excv = sm_exc[j + 1];   // LDS prefetch, off-path

            // ---- stage-2 half-chain ----
            // LO lanes: exact seed from d1. HI lanes: xin==0 forever -> d1n=d1o=0,
            // so seed is 0 and the q*eprev term restores exactness.
            float d1n = fmaf(ALPHA, d1o, AAC * xin);
            float nprev = d1o;
            float nwp   = d1n;
            float y = 0.f;
            #pragma unroll
            for (int k = 0; k < 19; k++) {
                float cbase = fmaf(ALPHA, n[k], nprev);      // imm-form
                float cc    = fmaf(q[k], eprev, cbase);      // e_prev fold
                float nw    = fmaf(-ALPHA, nwp, cc);         // 4-cyc chain
                y = fmaf(nw, breg[k], y);
                nprev = n[k];
                n[k]  = nw;
                nwp   = nw;
            }
            d1o = d1n;

            // e = new_18 (LO final nw); HI lanes fetch it for next sample's fold
            float u = fmaf(cb, nwp, y);                      // LO: y + cb*e; HI: y
            eprev = __shfl_sync(0xffffffffu, nwp, lane & 3);

            // single gather stage: 8 partials -> per-tap sums -> Pade combine
            float g0 = __shfl_sync(0xffffffffu, u, 0);
            float g1 = __shfl_sync(0xffffffffu, u, 1);
            float g2 = __shfl_sync(0xffffffffu, u, 2);
            float g3 = __shfl_sync(0xffffffffu, u, 3);
            float g4 = __shfl_sync(0xffffffffu, u, 4);
            float g5 = __shfl_sync(0xffffffffu, u, 5);
            float g6 = __shfl_sync(0xffffffffu, u, 6);
            float g7 = __shfl_sync(0xffffffffu, u, 7);
            float yt0 = g0 + g4;
            float yt1 = g1 + g5;
            float yt2 = g2 + g6;
            float yt3 = g3 + g7;
            float sA = fmaf(P3C, yt2, P1C * yt0);
            float sB = fmaf(P4C, yt3, P2C * yt1);
            float x2 = y1 + (sA - sB);
            float y2 = x2 + (sA + sB);
            if (lane == 0) wout[i] = y2;

            // next-sample tap inputs (LO lanes only): [x2, fy0, fy1, fy2]
            xin = (lane == 0) ? x2
                : (lane == 1) ? yt0
                : (lane == 2) ? yt1
                : (lane == 3) ? yt2
                : 0.f;
        }
    }
}

// ==================================================================
// K4: sum periodic + aperiodic channels into output
// ==================================================================
__global__ void k_sum(float* __restrict__ out)
{
    int i = blockIdx.x * 256 + threadIdx.x;
    if (i < BB * NN) out[i] = g_wav[i] + g_wav[BB * NN + i];
}

// ==================================================================
extern "C" void kernel_launch(void* const* d_in, const int* in_sizes, int n_in,
                              void* d_out, int out_size)
{
    const float* mceps = (const float*)d_in[0];
    const float* apdcs = (const float*)d_in[1];
    const float* f0s   = (const float*)d_in[2];
    const float* noise = (const float*)d_in[3];
    const float* Wm  = (const float*)d_in[4];
    const float* bm  = (const float*)d_in[5];
    const float* Wa  = (const float*)d_in[6];
    const float* ba  = (const float*)d_in[7];
    const float* Wf  = (const float*)d_in[8];
    const float* bf  = (const float*)d_in[9];
    const float* Wpa = (const float*)d_in[10];
    const float* bpa = (const float*)d_in[11];
    const float* Wpp = (const float*)d_in[12];
    const float* bpp = (const float*)d_in[13];
    const float* Wrp = (const float*)d_in[14];
    const float* brp = (const float*)d_in[15];
    const float* Wra = (const float*)d_in[16];
    const float* bra = (const float*)d_in[17];
    const float* Wap = (const float*)d_in[18];

    k_frontend<<<BB * TT, 256>>>(mceps, apdcs, f0s,
                                 Wm, bm, Wa, ba, Wf, bf,
                                 Wpa, bpa, Wpp, bpp,
                                 Wrp, brp, Wra, bra, Wap);
    k_pulse<<<BB, 256>>>();
    k_mlsa<<<NCH, 32>>>(noise);
    k_sum<<<(BB * NN + 255) / 256, 256>>>((float*)d_out);
}

// round 9
// speedup vs baseline: 1.3806x; 1.3806x over previous
#include <cuda_runtime.h>
#include <math.h>

// ---------------- problem constants ----------------
#define BB    4
#define TT    200
#define HOP   120
#define NN    24000          // T*HOP
#define M1    40
#define A1    5
#define HID   256
#define COND  192
#define NCH   8              // 2B channels (0..3 periodic, 4..7 aperiodic)

#define ALPHA 0.466f
#define AAC   0.782844f      // 1 - ALPHA^2
#define P1C   0.4999273f
#define P2C   0.1067005f
#define P3C   0.00956526f
#define P4C   0.0003041358f
#define SRF   24000.0f

// ---------------- scratch (no allocations allowed) ----------------
__device__ float g_bcoef[NCH * TT * M1];   // MLSA coefficients per channel/frame
__device__ float g_eb0[NCH * TT];          // exp(b[0]) per channel/frame
__device__ float g_b1[NCH * TT];           // b[1] per channel/frame
__device__ float g_f0[BB * TT];            // denormed f0 per batch/frame
__device__ float g_exc[BB * NN];           // periodic excitation (0.5 * pulse)
__device__ float g_wav[NCH * NN];          // per-channel filtered waveform
// tree-scan levels: 24000,12000,6000,3000,1500,750,375,187,93,46,23,11,5,2,1
#define SCAN_TOTAL 47993
__device__ float g_scanbuf[BB * SCAN_TOTAL];

// ==================================================================
// K1: dense frontend: feature embed -> cond -> mel-cepstra -> mc2b
// ==================================================================
__global__ __launch_bounds__(256) void k_frontend(
    const float* __restrict__ mceps, const float* __restrict__ apdcs,
    const float* __restrict__ f0s,
    const float* __restrict__ Wm,  const float* __restrict__ bm,
    const float* __restrict__ Wa,  const float* __restrict__ ba,
    const float* __restrict__ Wf,  const float* __restrict__ bf,
    const float* __restrict__ Wpa, const float* __restrict__ bpa,
    const float* __restrict__ Wpp, const float* __restrict__ bpp,
    const float* __restrict__ Wrp, const float* __restrict__ brp,
    const float* __restrict__ Wra, const float* __restrict__ bra,
    const float* __restrict__ Wap)
{
    int bt = blockIdx.x;            // 0..799
    int b  = bt / TT;
    int t  = bt % TT;
    int tid = threadIdx.x;

    __shared__ float feat[48];      // mcep[40] | apdc[5] | f0
    __shared__ float hsm[HID];
    __shared__ float cam[COND], cpm[COND];
    __shared__ float mcp[M1], mca[M1];

    if (tid < M1)            feat[tid] = mceps[bt * M1 + tid];
    else if (tid < M1 + A1)  feat[tid] = apdcs[bt * A1 + (tid - M1)];
    else if (tid == 45)      feat[45]  = f0s[bt];
    __syncthreads();

    {
        float s = bm[tid] + ba[tid] + bf[tid];
        #pragma unroll 8
        for (int i = 0; i < M1; i++) s = fmaf(feat[i], Wm[i * HID + tid], s);
        #pragma unroll
        for (int i = 0; i < A1; i++) s = fmaf(feat[M1 + i], Wa[i * HID + tid], s);
        s = fmaf(feat[45], Wf[tid], s);
        hsm[tid] = s;
    }
    __syncthreads();

    if (tid < COND) {
        float sa = bpa[tid], sp = bpp[tid];
        #pragma unroll 8
        for (int i = 0; i < HID; i++) {
            float h = hsm[i];
            sa = fmaf(h, Wpa[i * COND + tid], sa);
            sp = fmaf(h, Wpp[i * COND + tid], sp);
        }
        cam[tid] = sa;
        cpm[tid] = sp;
    }
    __syncthreads();

    if (tid < M1) {
        float rp = brp[tid], ra = bra[tid];
        #pragma unroll 8
        for (int i = 0; i < COND; i++) {
            rp = fmaf(cpm[i], Wrp[i * M1 + tid], rp);
            ra = fmaf(cam[i], Wra[i * M1 + tid], ra);
        }
        float apm = 0.f;
        #pragma unroll
        for (int i = 0; i < A1; i++) apm = fmaf(feat[M1 + i], Wap[i * M1 + tid], apm);
        float sp = feat[tid];
        mcp[tid] = sp + 0.1f * tanhf(rp);
        mca[tid] = sp + 0.1f * tanhf(ra) + apm;
    }
    __syncthreads();

    if (tid < 2) {
        const float* mc = (tid == 0) ? mcp : mca;
        int ch = (tid == 0) ? b : (4 + b);
        float* dst = g_bcoef + (ch * TT + t) * M1;
        float bbv = 0.f, b1v = 0.f;
        #pragma unroll
        for (int m = M1 - 1; m >= 0; m--) {
            bbv = fmaf(-ALPHA, bbv, mc[m]);
            dst[m] = bbv;
            if (m == 1) b1v = bbv;
        }
        g_eb0[ch * TT + t] = expf(bbv);
        g_b1[ch * TT + t]  = b1v;
        if (tid == 0) g_f0[b * TT + t] = expf(fmaf(feat[45], 0.25f, 5.0f));
    }
}

// ==================================================================
// K2: pulse excitation — bit-exact replication of JAX associative_scan
// (odd/even recursive tree lowering of jnp.cumsum)
// ==================================================================
__global__ __launch_bounds__(256) void k_pulse()
{
    const int b   = blockIdx.x;
    const int tid = threadIdx.x;
    const int NTH = blockDim.x;

    const int ln[15] = {24000,12000,6000,3000,1500,750,375,187,93,46,23,11,5,2,1};
    int off[15];
    off[0] = 0;
    #pragma unroll
    for (int k = 1; k < 15; k++) off[k] = off[k-1] + ln[k-1];

    float* buf = g_scanbuf + b * SCAN_TOTAL;

    for (int i = tid; i < NN; i += NTH)
        buf[i] = g_f0[b * TT + i / HOP] / SRF;
    __syncthreads();

    for (int k = 0; k < 14; k++) {
        const float* src = buf + off[k];
        float*       dst = buf + off[k+1];
        const int nn1 = ln[k+1];
        for (int i = tid; i < nn1; i += NTH)
            dst[i] = src[2*i] + src[2*i+1];
        __syncthreads();
    }

    for (int k = 13; k >= 0; k--) {
        float*       a = buf + off[k];
        const float* s = buf + off[k+1];
        const int n = ln[k];
        for (int i = tid; i < n; i += NTH) {
            float v;
            if (i & 1)            v = s[i >> 1];
            else if (i == 0)      v = a[0];
            else                  v = s[(i >> 1) - 1] + a[i];
            a[i] = v;
        }
        __syncthreads();
    }

    for (int i = tid; i < NN; i += NTH) {
        float w  = floorf(buf[i]);
        float wp = (i == 0) ? 0.f : floorf(buf[i-1]);
        float f  = g_f0[b * TT + i / HOP];
        float amp = 0.5f * sqrtf(SRF / fmaxf(f, 1.0f));
        g_exc[b * NN + i] = (w > wp) ? amp : 0.f;
    }
}

// ==================================================================
// K3: MLSA synthesis filter scan — ONE WARP PER CHANNEL.
//   lanes 0..3 : stage-2 Pade tap p = lane (38-reg delay line, SIMT lockstep)
//   all lanes  : stage-1 filter replicated (y1 in-register everywhere)
//   exchange   : 4x shfl.idx gather + redundant Pade reduce on all lanes
// BRANCH-FREE inner loop (ptxas emits BSSY/BSYNC for C++ ifs: 33-56 cyc/ea):
//   - excitation staged per frame into sm_exc[HOP+1] -> unconditional LDS
//   - y2 identical on all lanes -> unconditional same-address store
//   - xin for lane p>=1 taken from already-gathered t_{p-1} (no shfl_up)
// ==================================================================
__global__ __launch_bounds__(32, 1) void k_mlsa(const float* __restrict__ noise)
{
    const int c    = blockIdx.x;          // channel
    const int lane = threadIdx.x;         // taps on lanes 0..3

    __shared__ float sm_exc[HOP + 8];     // +1 lookahead, padded

    // ---- stage-2 tap state ----
    float n[38];
    #pragma unroll
    for (int j = 0; j < 38; j++) n[j] = 0.f;
    float breg[38];
    float d1o = 0.f, xin = 0.f;

    // ---- stage-1 state (replicated on every lane) ----
    float x1p = 0.f, npt0 = 0.f, npt1 = 0.f, npt2 = 0.f;
    float na0 = 0.f, na1 = 0.f, na2 = 0.f, na3 = 0.f;

    const float* bc  = g_bcoef + c * TT * M1;
    const bool periodic = (c < 4);
    const float* src = periodic ? (g_exc + c * NN) : (noise + (c - 4) * NN);
    const float scl  = periodic ? 1.0f : 0.5f;
    float* wout = g_wav + c * NN;

    for (int fr = 0; fr < TT; fr++) {
        const float* bf_ = bc + fr * M1;
        const float eb0 = g_eb0[c * TT + fr];
        const float b1  = g_b1[c * TT + fr];
        #pragma unroll
        for (int j = 0; j < 38; j++) breg[j] = bf_[2 + j];   // broadcast loads

        // stage excitation tile: 120 samples + 1 lookahead (per-frame, cold)
        __syncwarp();
        if (lane < 30) {
            float4 v = *reinterpret_cast<const float4*>(src + fr * HOP + lane * 4);
            float4 w;
            w.x = v.x * scl; w.y = v.y * scl; w.z = v.z * scl; w.w = v.w * scl;
            reinterpret_cast<float4*>(sm_exc)[lane] = w;
        } else if (lane == 30) {
            int nx = fr * HOP + HOP;
            sm_exc[HOP] = (nx < NN) ? src[nx] * scl : 0.f;
        }
        __syncwarp();

        float excv = sm_exc[0];
        const int base = fr * HOP;

        #pragma unroll 2
        for (int j = 0; j < HOP; j++) {
            // ---- stage-1 (mlsadf1), replicated on all lanes ----
            float x  = excv * eb0;
            float m0 = fmaf(ALPHA, na0, AAC * x1p);
            float m1 = fmaf(ALPHA, na1, AAC * npt0);
            float m2 = fmaf(ALPHA, na2, AAC * npt1);
            float m3 = fmaf(ALPHA, na3, AAC * npt2);
            na0 = m0; na1 = m1; na2 = m2; na3 = m3;
            float p0 = m0 * b1, p1 = m1 * b1, p2 = m2 * b1, p3 = m3 * b1;
            float sA1 = fmaf(P3C, p2, P1C * p0);
            float sB1 = fmaf(P4C, p3, P2C * p1);
            float x1 = x + (sA1 - sB1);
            float y1 = x1 + (sA1 + sB1);
            x1p = x1; npt0 = p0; npt1 = p1; npt2 = p2;
            excv = sm_exc[j + 1];                  // unconditional LDS prefetch

            // ---- stage-2 tap (mlsafir order recurrence), lane = tap ----
            float d1n = fmaf(ALPHA, d1o, AAC * xin);
            float pm1 = n[0];
            float nw  = fmaf(-ALPHA, d1n, fmaf(ALPHA, n[0], d1o));
            float y   = nw * breg[0];
            n[0] = nw;
            #pragma unroll
            for (int m = 1; m < 38; m++) {
                float cc = fmaf(ALPHA, n[m], pm1);   // off-chain (imm-form)
                pm1 = n[m];
                nw  = fmaf(-ALPHA, nw, cc);          // 4-cyc chain (imm-form)
                y   = fmaf(nw, breg[m], y);          // off-chain accum
                n[m] = nw;
            }
            d1o = d1n;

            // ---- cross-tap exchange + Pade reduce (all lanes, converged) ----
            float t0 = __shfl_sync(0xffffffffu, y, 0);
            float t1 = __shfl_sync(0xffffffffu, y, 1);
            float t2 = __shfl_sync(0xffffffffu, y, 2);
            float t3 = __shfl_sync(0xffffffffu, y, 3);
            float sA = fmaf(P3C, t2, P1C * t0);
            float sB = fmaf(P4C, t3, P2C * t1);
            float x2 = (y1 + sA) - sB;
            float y2 = x2 + (sA + sB);
            wout[base + j] = y2;                   // identical on all lanes

            // next-sample tap inputs: pt2 = [x2, fy0, fy1, fy2]
            // lane p>=1 needs y of lane p-1 == t_{p-1} (already gathered)
            xin = (lane == 0) ? x2
                : (lane == 1) ? t0
                : (lane == 2) ? t1
                : t2;
        }
    }
}

// ==================================================================
// K4: sum periodic + aperiodic channels into output
// ==================================================================
__global__ void k_sum(float* __restrict__ out)
{
    int i = blockIdx.x * 256 + threadIdx.x;
    if (i < BB * NN) out[i] = g_wav[i] + g_wav[BB * NN + i];
}

// ==================================================================
extern "C" void kernel_launch(void* const* d_in, const int* in_sizes, int n_in,
                              void* d_out, int out_size)
{
    const float* mceps = (const float*)d_in[0];
    const float* apdcs = (const float*)d_in[1];
    const float* f0s   = (const float*)d_in[2];
    const float* noise = (const float*)d_in[3];
    const float* Wm  = (const float*)d_in[4];
    const float* bm  = (const float*)d_in[5];
    const float* Wa  = (const float*)d_in[6];
    const float* ba  = (const float*)d_in[7];
    const float* Wf  = (const float*)d_in[8];
    const float* bf  = (const float*)d_in[9];
    const float* Wpa = (const float*)d_in[10];
    const float* bpa = (const float*)d_in[11];
    const float* Wpp = (const float*)d_in[12];
    const float* bpp = (const float*)d_in[13];
    const float* Wrp = (const float*)d_in[14];
    const float* brp = (const float*)d_in[15];
    const float* Wra = (const float*)d_in[16];
    const float* bra = (const float*)d_in[17];
    const float* Wap = (const float*)d_in[18];

    k_frontend<<<BB * TT, 256>>>(mceps, apdcs, f0s,
                                 Wm, bm, Wa, ba, Wf, bf,
                                 Wpa, bpa, Wpp, bpp,
                                 Wrp, brp, Wra, bra, Wap);
    k_pulse<<<BB, 256>>>();
    k_mlsa<<<NCH, 32>>>(noise);
    k_sum<<<(BB * NN + 255) / 256, 256>>>((float*)d_out);
}

// round 10
// speedup vs baseline: 6.2226x; 4.5072x over previous
#include <cuda_runtime.h>
#include <math.h>

// ---------------- problem constants ----------------
#define BB    4
#define TT    200
#define HOP   120
#define NN    24000          // T*HOP
#define M1    40
#define A1    5
#define HID   256
#define COND  192
#define NCH   8              // 2B channels (0..3 periodic, 4..7 aperiodic)

#define ALPHA 0.466f
#define AAC   0.782844f      // 1 - ALPHA^2
#define P1C   0.4999273f
#define P2C   0.1067005f
#define P3C   0.00956526f
#define P4C   0.0003041358f
#define SRF   24000.0f

// time-segmentation of the MLSA scan
#define SEG     8            // segments per channel
#define SEGLEN  3000         // NN / SEG (25 frames)
#define WARM    3000         // warm-up samples (25 frames), zero-state start

// ---------------- scratch (no allocations allowed) ----------------
__device__ float g_bcoef[NCH * TT * M1];   // MLSA coefficients per channel/frame
__device__ float g_eb0[NCH * TT];          // exp(b[0]) per channel/frame
__device__ float g_b1[NCH * TT];           // b[1] per channel/frame
__device__ float g_f0[BB * TT];            // denormed f0 per batch/frame
__device__ float g_exc[BB * NN];           // periodic excitation (0.5 * pulse)
__device__ float g_wav[NCH * NN];          // per-channel filtered waveform
// tree-scan levels: 24000,12000,6000,3000,1500,750,375,187,93,46,23,11,5,2,1
#define SCAN_TOTAL 47993
__device__ float g_scanbuf[BB * SCAN_TOTAL];

// ==================================================================
// K1: dense frontend: feature embed -> cond -> mel-cepstra -> mc2b
// ==================================================================
__global__ __launch_bounds__(256) void k_frontend(
    const float* __restrict__ mceps, const float* __restrict__ apdcs,
    const float* __restrict__ f0s,
    const float* __restrict__ Wm,  const float* __restrict__ bm,
    const float* __restrict__ Wa,  const float* __restrict__ ba,
    const float* __restrict__ Wf,  const float* __restrict__ bf,
    const float* __restrict__ Wpa, const float* __restrict__ bpa,
    const float* __restrict__ Wpp, const float* __restrict__ bpp,
    const float* __restrict__ Wrp, const float* __restrict__ brp,
    const float* __restrict__ Wra, const float* __restrict__ bra,
    const float* __restrict__ Wap)
{
    int bt = blockIdx.x;            // 0..799
    int b  = bt / TT;
    int t  = bt % TT;
    int tid = threadIdx.x;

    __shared__ float feat[48];      // mcep[40] | apdc[5] | f0
    __shared__ float hsm[HID];
    __shared__ float cam[COND], cpm[COND];
    __shared__ float mcp[M1], mca[M1];

    if (tid < M1)            feat[tid] = mceps[bt * M1 + tid];
    else if (tid < M1 + A1)  feat[tid] = apdcs[bt * A1 + (tid - M1)];
    else if (tid == 45)      feat[45]  = f0s[bt];
    __syncthreads();

    {
        float s = bm[tid] + ba[tid] + bf[tid];
        #pragma unroll 8
        for (int i = 0; i < M1; i++) s = fmaf(feat[i], Wm[i * HID + tid], s);
        #pragma unroll
        for (int i = 0; i < A1; i++) s = fmaf(feat[M1 + i], Wa[i * HID + tid], s);
        s = fmaf(feat[45], Wf[tid], s);
        hsm[tid] = s;
    }
    __syncthreads();

    if (tid < COND) {
        float sa = bpa[tid], sp = bpp[tid];
        #pragma unroll 8
        for (int i = 0; i < HID; i++) {
            float h = hsm[i];
            sa = fmaf(h, Wpa[i * COND + tid], sa);
            sp = fmaf(h, Wpp[i * COND + tid], sp);
        }
        cam[tid] = sa;
        cpm[tid] = sp;
    }
    __syncthreads();

    if (tid < M1) {
        float rp = brp[tid], ra = bra[tid];
        #pragma unroll 8
        for (int i = 0; i < COND; i++) {
            rp = fmaf(cpm[i], Wrp[i * M1 + tid], rp);
            ra = fmaf(cam[i], Wra[i * M1 + tid], ra);
        }
        float apm = 0.f;
        #pragma unroll
        for (int i = 0; i < A1; i++) apm = fmaf(feat[M1 + i], Wap[i * M1 + tid], apm);
        float sp = feat[tid];
        mcp[tid] = sp + 0.1f * tanhf(rp);
        mca[tid] = sp + 0.1f * tanhf(ra) + apm;
    }
    __syncthreads();

    if (tid < 2) {
        const float* mc = (tid == 0) ? mcp : mca;
        int ch = (tid == 0) ? b : (4 + b);
        float* dst = g_bcoef + (ch * TT + t) * M1;
        float bbv = 0.f, b1v = 0.f;
        #pragma unroll
        for (int m = M1 - 1; m >= 0; m--) {
            bbv = fmaf(-ALPHA, bbv, mc[m]);
            dst[m] = bbv;
            if (m == 1) b1v = bbv;
        }
        g_eb0[ch * TT + t] = expf(bbv);
        g_b1[ch * TT + t]  = b1v;
        if (tid == 0) g_f0[b * TT + t] = expf(fmaf(feat[45], 0.25f, 5.0f));
    }
}

// ==================================================================
// K2: pulse excitation — bit-exact replication of JAX associative_scan
// (odd/even recursive tree lowering of jnp.cumsum)
// ==================================================================
__global__ __launch_bounds__(256) void k_pulse()
{
    const int b   = blockIdx.x;
    const int tid = threadIdx.x;
    const int NTH = blockDim.x;

    const int ln[15] = {24000,12000,6000,3000,1500,750,375,187,93,46,23,11,5,2,1};
    int off[15];
    off[0] = 0;
    #pragma unroll
    for (int k = 1; k < 15; k++) off[k] = off[k-1] + ln[k-1];

    float* buf = g_scanbuf + b * SCAN_TOTAL;

    for (int i = tid; i < NN; i += NTH)
        buf[i] = g_f0[b * TT + i / HOP] / SRF;
    __syncthreads();

    for (int k = 0; k < 14; k++) {
        const float* src = buf + off[k];
        float*       dst = buf + off[k+1];
        const int nn1 = ln[k+1];
        for (int i = tid; i < nn1; i += NTH)
            dst[i] = src[2*i] + src[2*i+1];
        __syncthreads();
    }

    for (int k = 13; k >= 0; k--) {
        float*       a = buf + off[k];
        const float* s = buf + off[k+1];
        const int n = ln[k];
        for (int i = tid; i < n; i += NTH) {
            float v;
            if (i & 1)            v = s[i >> 1];
            else if (i == 0)      v = a[0];
            else                  v = s[(i >> 1) - 1] + a[i];
            a[i] = v;
        }
        __syncthreads();
    }

    for (int i = tid; i < NN; i += NTH) {
        float w  = floorf(buf[i]);
        float wp = (i == 0) ? 0.f : floorf(buf[i-1]);
        float f  = g_f0[b * TT + i / HOP];
        float amp = 0.5f * sqrtf(SRF / fmaxf(f, 1.0f));
        g_exc[b * NN + i] = (w > wp) ? amp : 0.f;
    }
}

// ==================================================================
// K3: MLSA synthesis filter scan — ONE WARP PER (channel, time-segment).
// Inner-loop body identical to the measured-good R7 kernel.
// Each segment starts from ZERO state WARM samples before its write
// window; the filter is a stable linear system, so the truncated-past
// response decays below 1e-6 within the warm-up, making segments
// independent to well under the 1e-3 threshold. Segment 0 is exact.
//   lanes 0..3 : stage-2 Pade tap p = lane (38-reg delay line)
//   all lanes  : stage-1 replicated; exchange via 4x shfl + shfl_up
// ==================================================================
__global__ __launch_bounds__(32, 1) void k_mlsa(const float* __restrict__ noise)
{
    const int blk  = blockIdx.x;          // 0..NCH*SEG-1
    const int c    = blk / SEG;           // channel
    const int s    = blk % SEG;           // time segment
    const int lane = threadIdx.x;         // taps on lanes 0..3

    const int wbeg = s * SEGLEN;                      // first written sample
    const int wend = wbeg + SEGLEN;
    const int abeg = (s == 0) ? 0 : (wbeg - WARM);    // processing start
    const int fr0  = abeg / HOP;
    const int frw  = wbeg / HOP;
    const int fr1  = wend / HOP;

    // ---- stage-2 tap state ----
    float n[38];
    #pragma unroll
    for (int j = 0; j < 38; j++) n[j] = 0.f;
    float breg[38];
    float d1o = 0.f, xin = 0.f;

    // ---- stage-1 state (replicated on every lane) ----
    float x1p = 0.f, npt0 = 0.f, npt1 = 0.f, npt2 = 0.f;
    float na0 = 0.f, na1 = 0.f, na2 = 0.f, na3 = 0.f;

    const float* bc  = g_bcoef + c * TT * M1;
    const bool periodic = (c < 4);
    const float* src = periodic ? (g_exc + c * NN) : (noise + (c - 4) * NN);
    const float scl  = periodic ? 1.0f : 0.5f;
    float* wout = g_wav + c * NN;

    float excv = src[abeg] * scl;         // prefetch first sample

    for (int fr = fr0; fr < fr1; fr++) {
        const float* bf_ = bc + fr * M1;
        const float eb0 = g_eb0[c * TT + fr];
        const float b1  = g_b1[c * TT + fr];
        #pragma unroll
        for (int j = 0; j < 38; j++) breg[j] = bf_[2 + j];   // broadcast loads

        const bool wr = (fr >= frw);
        const int base = fr * HOP;

        for (int j = 0; j < HOP; j++) {
            const int i = base + j;

            // ---- stage-1 (mlsadf1), replicated on all lanes ----
            float x  = excv * eb0;
            float m0 = fmaf(ALPHA, na0, AAC * x1p);
            float m1 = fmaf(ALPHA, na1, AAC * npt0);
            float m2 = fmaf(ALPHA, na2, AAC * npt1);
            float m3 = fmaf(ALPHA, na3, AAC * npt2);
            na0 = m0; na1 = m1; na2 = m2; na3 = m3;
            float p0 = m0 * b1, p1 = m1 * b1, p2 = m2 * b1, p3 = m3 * b1;
            float sA1 = fmaf(P3C, p2, P1C * p0);
            float sB1 = fmaf(P4C, p3, P2C * p1);
            float x1 = x + (sA1 - sB1);
            float y1 = x1 + (sA1 + sB1);
            x1p = x1; npt0 = p0; npt1 = p1; npt2 = p2;

            // prefetch next excitation sample (off critical path)
            if (i + 1 < NN) excv = src[i + 1] * scl;

            // ---- stage-2 tap (mlsafir order recurrence), lane = tap ----
            float d1n = fmaf(ALPHA, d1o, AAC * xin);
            float pm1 = n[0];
            float nw  = fmaf(-ALPHA, d1n, fmaf(ALPHA, n[0], d1o));
            float y   = nw * breg[0];
            n[0] = nw;
            #pragma unroll
            for (int m = 1; m < 38; m++) {
                float cc = fmaf(ALPHA, n[m], pm1);   // off-chain
                pm1 = n[m];
                nw  = fmaf(-ALPHA, nw, cc);          // 4-cyc chain
                y   = fmaf(nw, breg[m], y);          // off-chain accum
                n[m] = nw;
            }
            d1o = d1n;

            // ---- cross-tap exchange + Pade reduce (all lanes, converged) ----
            float t0 = __shfl_sync(0xffffffffu, y, 0);
            float t1 = __shfl_sync(0xffffffffu, y, 1);
            float t2 = __shfl_sync(0xffffffffu, y, 2);
            float t3 = __shfl_sync(0xffffffffu, y, 3);
            float sA = fmaf(P3C, t2, P1C * t0);
            float sB = fmaf(P4C, t3, P2C * t1);
            float x2 = y1 + (sA - sB);
            float y2 = x2 + (sA + sB);
            if (lane == 0 && wr) wout[i] = y2;       // predicated store

            // next-sample tap inputs: pt2 = [x2, fy0, fy1, fy2]
            float up = __shfl_up_sync(0xffffffffu, y, 1);
            xin = (lane == 0) ? x2 : up;
        }
    }
}

// ==================================================================
// K4: sum periodic + aperiodic channels into output
// ==================================================================
__global__ void k_sum(float* __restrict__ out)
{
    int i = blockIdx.x * 256 + threadIdx.x;
    if (i < BB * NN) out[i] = g_wav[i] + g_wav[BB * NN + i];
}

// ==================================================================
extern "C" void kernel_launch(void* const* d_in, const int* in_sizes, int n_in,
                              void* d_out, int out_size)
{
    const float* mceps = (const float*)d_in[0];
    const float* apdcs = (const float*)d_in[1];
    const float* f0s   = (const float*)d_in[2];
    const float* noise = (const float*)d_in[3];
    const float* Wm  = (const float*)d_in[4];
    const float* bm  = (const float*)d_in[5];
    const float* Wa  = (const float*)d_in[6];
    const float* ba  = (const float*)d_in[7];
    const float* Wf  = (const float*)d_in[8];
    const float* bf  = (const float*)d_in[9];
    const float* Wpa = (const float*)d_in[10];
    const float* bpa = (const float*)d_in[11];
    const float* Wpp = (const float*)d_in[12];
    const float* bpp = (const float*)d_in[13];
    const float* Wrp = (const float*)d_in[14];
    const float* brp = (const float*)d_in[15];
    const float* Wra = (const float*)d_in[16];
    const float* bra = (const float*)d_in[17];
    const float* Wap = (const float*)d_in[18];

    k_frontend<<<BB * TT, 256>>>(mceps, apdcs, f0s,
                                 Wm, bm, Wa, ba, Wf, bf,
                                 Wpa, bpa, Wpp, bpp,
                                 Wrp, brp, Wra, bra, Wap);
    k_pulse<<<BB, 256>>>();
    k_mlsa<<<NCH * SEG, 32>>>(noise);
    k_sum<<<(BB * NN + 255) / 256, 256>>>((float*)d_out);
}

// round 12
// speedup vs baseline: 17.3173x; 2.7830x over previous
#include <cuda_runtime.h>
#include <math.h>

// ---------------- problem constants ----------------
#define BB    4
#define TT    200
#define HOP   120
#define NN    24000          // T*HOP
#define M1    40
#define A1    5
#define HID   256
#define COND  192
#define NCH   8              // 2B channels (0..3 periodic, 4..7 aperiodic)

#define ALPHA 0.466f
#define AAC   0.782844f      // 1 - ALPHA^2
#define P1C   0.4999273f
#define P2C   0.1067005f
#define P3C   0.00956526f
#define P4C   0.0003041358f
#define SRF   24000.0f

// time-segmentation of the MLSA scan
// Measured @ WARM=3000: truncation contribution <=1e-10 relative
// => decay rate >= 25/3000 per sample => WARM=1200 residual ~4e-5 << 1e-3.
#define SEG     50           // segments per channel (4 frames each)
#define SEGLEN  480          // NN / SEG
#define WARM    1200         // warm-up samples (10 frames), zero-state start

// ---------------- scratch (no allocations allowed) ----------------
__device__ float g_bcoef[NCH * TT * M1];   // MLSA coefficients per channel/frame
__device__ float g_eb0[NCH * TT];          // exp(b[0]) per channel/frame
__device__ float g_b1[NCH * TT];           // b[1] per channel/frame
__device__ float g_f0[BB * TT];            // denormed f0 per batch/frame
__device__ float g_exc[BB * NN];           // periodic excitation (0.5 * pulse)
__device__ float g_wav[NCH * NN];          // per-channel filtered waveform
// tree-scan levels: 24000,12000,6000,3000,1500,750,375,187,93,46,23,11,5,2,1
#define SCAN_TOTAL 47993
__device__ float g_scanbuf[BB * SCAN_TOTAL];

// ==================================================================
// K1: dense frontend: feature embed -> cond -> mel-cepstra -> mc2b
// ==================================================================
__global__ __launch_bounds__(256) void k_frontend(
    const float* __restrict__ mceps, const float* __restrict__ apdcs,
    const float* __restrict__ f0s,
    const float* __restrict__ Wm,  const float* __restrict__ bm,
    const float* __restrict__ Wa,  const float* __restrict__ ba,
    const float* __restrict__ Wf,  const float* __restrict__ bf,
    const float* __restrict__ Wpa, const float* __restrict__ bpa,
    const float* __restrict__ Wpp, const float* __restrict__ bpp,
    const float* __restrict__ Wrp, const float* __restrict__ brp,
    const float* __restrict__ Wra, const float* __restrict__ bra,
    const float* __restrict__ Wap)
{
    int bt = blockIdx.x;            // 0..799
    int b  = bt / TT;
    int t  = bt % TT;
    int tid = threadIdx.x;

    __shared__ float feat[48];      // mcep[40] | apdc[5] | f0
    __shared__ float hsm[HID];
    __shared__ float cam[COND], cpm[COND];
    __shared__ float mcp[M1], mca[M1];

    if (tid < M1)            feat[tid] = mceps[bt * M1 + tid];
    else if (tid < M1 + A1)  feat[tid] = apdcs[bt * A1 + (tid - M1)];
    else if (tid == 45)      feat[45]  = f0s[bt];
    __syncthreads();

    {
        float s = bm[tid] + ba[tid] + bf[tid];
        #pragma unroll 8
        for (int i = 0; i < M1; i++) s = fmaf(feat[i], Wm[i * HID + tid], s);
        #pragma unroll
        for (int i = 0; i < A1; i++) s = fmaf(feat[M1 + i], Wa[i * HID + tid], s);
        s = fmaf(feat[45], Wf[tid], s);
        hsm[tid] = s;
    }
    __syncthreads();

    if (tid < COND) {
        float sa = bpa[tid], sp = bpp[tid];
        #pragma unroll 8
        for (int i = 0; i < HID; i++) {
            float h = hsm[i];
            sa = fmaf(h, Wpa[i * COND + tid], sa);
            sp = fmaf(h, Wpp[i * COND + tid], sp);
        }
        cam[tid] = sa;
        cpm[tid] = sp;
    }
    __syncthreads();

    if (tid < M1) {
        float rp = brp[tid], ra = bra[tid];
        #pragma unroll 8
        for (int i = 0; i < COND; i++) {
            rp = fmaf(cpm[i], Wrp[i * M1 + tid], rp);
            ra = fmaf(cam[i], Wra[i * M1 + tid], ra);
        }
        float apm = 0.f;
        #pragma unroll
        for (int i = 0; i < A1; i++) apm = fmaf(feat[M1 + i], Wap[i * M1 + tid], apm);
        float sp = feat[tid];
        mcp[tid] = sp + 0.1f * tanhf(rp);
        mca[tid] = sp + 0.1f * tanhf(ra) + apm;
    }
    __syncthreads();

    if (tid < 2) {
        const float* mc = (tid == 0) ? mcp : mca;
        int ch = (tid == 0) ? b : (4 + b);
        float* dst = g_bcoef + (ch * TT + t) * M1;
        float bbv = 0.f, b1v = 0.f;
        #pragma unroll
        for (int m = M1 - 1; m >= 0; m--) {
            bbv = fmaf(-ALPHA, bbv, mc[m]);
            dst[m] = bbv;
            if (m == 1) b1v = bbv;
        }
        g_eb0[ch * TT + t] = expf(bbv);
        g_b1[ch * TT + t]  = b1v;
        if (tid == 0) g_f0[b * TT + t] = expf(fmaf(feat[45], 0.25f, 5.0f));
    }
}

// ==================================================================
// K2: pulse excitation — bit-exact replication of JAX associative_scan
// (odd/even recursive tree lowering of jnp.cumsum)
// ==================================================================
__global__ __launch_bounds__(256) void k_pulse()
{
    const int b   = blockIdx.x;
    const int tid = threadIdx.x;
    const int NTH = blockDim.x;

    const int ln[15] = {24000,12000,6000,3000,1500,750,375,187,93,46,23,11,5,2,1};
    int off[15];
    off[0] = 0;
    #pragma unroll
    for (int k = 1; k < 15; k++) off[k] = off[k-1] + ln[k-1];

    float* buf = g_scanbuf + b * SCAN_TOTAL;

    for (int i = tid; i < NN; i += NTH)
        buf[i] = g_f0[b * TT + i / HOP] / SRF;
    __syncthreads();

    for (int k = 0; k < 14; k++) {
        const float* src = buf + off[k];
        float*       dst = buf + off[k+1];
        const int nn1 = ln[k+1];
        for (int i = tid; i < nn1; i += NTH)
            dst[i] = src[2*i] + src[2*i+1];
        __syncthreads();
    }

    for (int k = 13; k >= 0; k--) {
        float*       a = buf + off[k];
        const float* s = buf + off[k+1];
        const int n = ln[k];
        for (int i = tid; i < n; i += NTH) {
            float v;
            if (i & 1)            v = s[i >> 1];
            else if (i == 0)      v = a[0];
            else                  v = s[(i >> 1) - 1] + a[i];
            a[i] = v;
        }
        __syncthreads();
    }

    for (int i = tid; i < NN; i += NTH) {
        float w  = floorf(buf[i]);
        float wp = (i == 0) ? 0.f : floorf(buf[i-1]);
        float f  = g_f0[b * TT + i / HOP];
        float amp = 0.5f * sqrtf(SRF / fmaxf(f, 1.0f));
        g_exc[b * NN + i] = (w > wp) ? amp : 0.f;
    }
}

// ==================================================================
// K3: MLSA synthesis filter scan — ONE WARP PER (channel, time-segment).
// Inner-loop body identical to the measured-good R7/R10 kernel.
// Each segment starts from ZERO state WARM samples before its write
// window, CLAMPED to sample 0 (early segments get a shorter warm-up
// that is EXACT, since sample 0 is the true zero initial state).
//   lanes 0..3 : stage-2 Pade tap p = lane (38-reg delay line)
//   all lanes  : stage-1 replicated; exchange via 4x shfl + shfl_up
// ==================================================================
__global__ __launch_bounds__(32, 1) void k_mlsa(const float* __restrict__ noise)
{
    const int blk  = blockIdx.x;          // 0..NCH*SEG-1
    const int c    = blk / SEG;           // channel
    const int s    = blk % SEG;           // time segment
    const int lane = threadIdx.x;         // taps on lanes 0..3

    const int wbeg = s * SEGLEN;                      // first written sample
    const int wend = wbeg + SEGLEN;
    int abeg = wbeg - WARM;                           // processing start
    if (abeg < 0) abeg = 0;                           // clamp (exact for early segs)
    const int fr0  = abeg / HOP;
    const int frw  = wbeg / HOP;
    const int fr1  = wend / HOP;

    // ---- stage-2 tap state ----
    float n[38];
    #pragma unroll
    for (int j = 0; j < 38; j++) n[j] = 0.f;
    float breg[38];
    float d1o = 0.f, xin = 0.f;

    // ---- stage-1 state (replicated on every lane) ----
    float x1p = 0.f, npt0 = 0.f, npt1 = 0.f, npt2 = 0.f;
    float na0 = 0.f, na1 = 0.f, na2 = 0.f, na3 = 0.f;

    const float* bc  = g_bcoef + c * TT * M1;
    const bool periodic = (c < 4);
    const float* src = periodic ? (g_exc + c * NN) : (noise + (c - 4) * NN);
    const float scl  = periodic ? 1.0f : 0.5f;
    float* wout = g_wav + c * NN;

    float excv = src[abeg] * scl;         // prefetch first sample

    for (int fr = fr0; fr < fr1; fr++) {
        const float* bf_ = bc + fr * M1;
        const float eb0 = g_eb0[c * TT + fr];
        const float b1  = g_b1[c * TT + fr];
        #pragma unroll
        for (int j = 0; j < 38; j++) breg[j] = bf_[2 + j];   // broadcast loads

        const bool wr = (fr >= frw);
        const int base = fr * HOP;

        for (int j = 0; j < HOP; j++) {
            const int i = base + j;

            // ---- stage-1 (mlsadf1), replicated on all lanes ----
            float x  = excv * eb0;
            float m0 = fmaf(ALPHA, na0, AAC * x1p);
            float m1 = fmaf(ALPHA, na1, AAC * npt0);
            float m2 = fmaf(ALPHA, na2, AAC * npt1);
            float m3 = fmaf(ALPHA, na3, AAC * npt2);
            na0 = m0; na1 = m1; na2 = m2; na3 = m3;
            float p0 = m0 * b1, p1 = m1 * b1, p2 = m2 * b1, p3 = m3 * b1;
            float sA1 = fmaf(P3C, p2, P1C * p0);
            float sB1 = fmaf(P4C, p3, P2C * p1);
            float x1 = x + (sA1 - sB1);
            float y1 = x1 + (sA1 + sB1);
            x1p = x1; npt0 = p0; npt1 = p1; npt2 = p2;

            // prefetch next excitation sample (off critical path)
            if (i + 1 < NN) excv = src[i + 1] * scl;

            // ---- stage-2 tap (mlsafir order recurrence), lane = tap ----
            float d1n = fmaf(ALPHA, d1o, AAC * xin);
            float pm1 = n[0];
            float nw  = fmaf(-ALPHA, d1n, fmaf(ALPHA, n[0], d1o));
            float y   = nw * breg[0];
            n[0] = nw;
            #pragma unroll
            for (int m = 1; m < 38; m++) {
                float cc = fmaf(ALPHA, n[m], pm1);   // off-chain
                pm1 = n[m];
                nw  = fmaf(-ALPHA, nw, cc);          // 4-cyc chain
                y   = fmaf(nw, breg[m], y);          // off-chain accum
                n[m] = nw;
            }
            d1o = d1n;

            // ---- cross-tap exchange + Pade reduce (all lanes, converged) ----
            float t0 = __shfl_sync(0xffffffffu, y, 0);
            float t1 = __shfl_sync(0xffffffffu, y, 1);
            float t2 = __shfl_sync(0xffffffffu, y, 2);
            float t3 = __shfl_sync(0xffffffffu, y, 3);
            float sA = fmaf(P3C, t2, P1C * t0);
            float sB = fmaf(P4C, t3, P2C * t1);
            float x2 = y1 + (sA - sB);
            float y2 = x2 + (sA + sB);
            if (lane == 0 && wr) wout[i] = y2;       // predicated store

            // next-sample tap inputs: pt2 = [x2, fy0, fy1, fy2]
            float up = __shfl_up_sync(0xffffffffu, y, 1);
            xin = (lane == 0) ? x2 : up;
        }
    }
}

// ==================================================================
// K4: sum periodic + aperiodic channels into output
// ==================================================================
__global__ void k_sum(float* __restrict__ out)
{
    int i = blockIdx.x * 256 + threadIdx.x;
    if (i < BB * NN) out[i] = g_wav[i] + g_wav[BB * NN + i];
}

// ==================================================================
extern "C" void kernel_launch(void* const* d_in, const int* in_sizes, int n_in,
                              void* d_out, int out_size)
{
    const float* mceps = (const float*)d_in[0];
    const float* apdcs = (const float*)d_in[1];
    const float* f0s   = (const float*)d_in[2];
    const float* noise = (const float*)d_in[3];
    const float* Wm  = (const float*)d_in[4];
    const float* bm  = (const float*)d_in[5];
    const float* Wa  = (const float*)d_in[6];
    const float* ba  = (const float*)d_in[7];
    const float* Wf  = (const float*)d_in[8];
    const float* bf  = (const float*)d_in[9];
    const float* Wpa = (const float*)d_in[10];
    const float* bpa = (const float*)d_in[11];
    const float* Wpp = (const float*)d_in[12];
    const float* bpp = (const float*)d_in[13];
    const float* Wrp = (const float*)d_in[14];
    const float* brp = (const float*)d_in[15];
    const float* Wra = (const float*)d_in[16];
    const float* bra = (const float*)d_in[17];
    const float* Wap = (const float*)d_in[18];

    k_frontend<<<BB * TT, 256>>>(mceps, apdcs, f0s,
                                 Wm, bm, Wa, ba, Wf, bf,
                                 Wpa, bpa, Wpp, bpp,
                                 Wrp, brp, Wra, bra, Wap);
    k_pulse<<<BB, 256>>>();
    k_mlsa<<<NCH * SEG, 32>>>(noise);
    k_sum<<<(BB * NN + 255) / 256, 256>>>((float*)d_out);
}

// round 13
// speedup vs baseline: 22.0710x; 1.2745x over previous
#include <cuda_runtime.h>
#include <math.h>

// ---------------- problem constants ----------------
#define BB    4
#define TT    200
#define HOP   120
#define NN    24000          // T*HOP
#define M1    40
#define A1    5
#define HID   256
#define COND  192
#define NCH   8              // 2B channels (0..3 periodic, 4..7 aperiodic)

#define ALPHA 0.466f
#define AAC   0.782844f      // 1 - ALPHA^2
#define P1C   0.4999273f
#define P2C   0.1067005f
#define P3C   0.00956526f
#define P4C   0.0003041358f
#define SRF   24000.0f

// time-segmentation of the MLSA scan
// Measured: truncation transient ~1e-8 relative at 1200 samples
// => decay rate ~0.0153/sample => WARM=720 residual ~1.6e-5 << 1e-3.
#define SEG     100          // segments per channel (2 frames each)
#define SEGLEN  240          // NN / SEG
#define WARM    720          // warm-up samples (6 frames), zero-state start

// ---------------- scratch (no allocations allowed) ----------------
__device__ float g_bcoef[NCH * TT * M1];   // MLSA coefficients per channel/frame
__device__ float g_eb0[NCH * TT];          // exp(b[0]) per channel/frame
__device__ float g_b1[NCH * TT];           // b[1] per channel/frame
__device__ float g_f0[BB * TT];            // denormed f0 per batch/frame
__device__ float g_exc[BB * NN];           // periodic excitation (0.5 * pulse)
// tree-scan levels: 24000,12000,6000,3000,1500,750,375,187,93,46,23,11,5,2,1
#define SCAN_TOTAL 47993
__device__ float g_scanbuf[BB * SCAN_TOTAL];

// ==================================================================
// K1: dense frontend: feature embed -> cond -> mel-cepstra -> mc2b
// ==================================================================
__global__ __launch_bounds__(256) void k_frontend(
    const float* __restrict__ mceps, const float* __restrict__ apdcs,
    const float* __restrict__ f0s,
    const float* __restrict__ Wm,  const float* __restrict__ bm,
    const float* __restrict__ Wa,  const float* __restrict__ ba,
    const float* __restrict__ Wf,  const float* __restrict__ bf,
    const float* __restrict__ Wpa, const float* __restrict__ bpa,
    const float* __restrict__ Wpp, const float* __restrict__ bpp,
    const float* __restrict__ Wrp, const float* __restrict__ brp,
    const float* __restrict__ Wra, const float* __restrict__ bra,
    const float* __restrict__ Wap)
{
    int bt = blockIdx.x;            // 0..799
    int b  = bt / TT;
    int t  = bt % TT;
    int tid = threadIdx.x;

    __shared__ float feat[48];      // mcep[40] | apdc[5] | f0
    __shared__ float hsm[HID];
    __shared__ float cam[COND], cpm[COND];
    __shared__ float mcp[M1], mca[M1];

    if (tid < M1)            feat[tid] = mceps[bt * M1 + tid];
    else if (tid < M1 + A1)  feat[tid] = apdcs[bt * A1 + (tid - M1)];
    else if (tid == 45)      feat[45]  = f0s[bt];
    __syncthreads();

    {
        float s = bm[tid] + ba[tid] + bf[tid];
        #pragma unroll 8
        for (int i = 0; i < M1; i++) s = fmaf(feat[i], Wm[i * HID + tid], s);
        #pragma unroll
        for (int i = 0; i < A1; i++) s = fmaf(feat[M1 + i], Wa[i * HID + tid], s);
        s = fmaf(feat[45], Wf[tid], s);
        hsm[tid] = s;
    }
    __syncthreads();

    if (tid < COND) {
        float sa = bpa[tid], sp = bpp[tid];
        #pragma unroll 8
        for (int i = 0; i < HID; i++) {
            float h = hsm[i];
            sa = fmaf(h, Wpa[i * COND + tid], sa);
            sp = fmaf(h, Wpp[i * COND + tid], sp);
        }
        cam[tid] = sa;
        cpm[tid] = sp;
    }
    __syncthreads();

    if (tid < M1) {
        float rp = brp[tid], ra = bra[tid];
        #pragma unroll 8
        for (int i = 0; i < COND; i++) {
            rp = fmaf(cpm[i], Wrp[i * M1 + tid], rp);
            ra = fmaf(cam[i], Wra[i * M1 + tid], ra);
        }
        float apm = 0.f;
        #pragma unroll
        for (int i = 0; i < A1; i++) apm = fmaf(feat[M1 + i], Wap[i * M1 + tid], apm);
        float sp = feat[tid];
        mcp[tid] = sp + 0.1f * tanhf(rp);
        mca[tid] = sp + 0.1f * tanhf(ra) + apm;
    }
    __syncthreads();

    if (tid < 2) {
        const float* mc = (tid == 0) ? mcp : mca;
        int ch = (tid == 0) ? b : (4 + b);
        float* dst = g_bcoef + (ch * TT + t) * M1;
        float bbv = 0.f, b1v = 0.f;
        #pragma unroll
        for (int m = M1 - 1; m >= 0; m--) {
            bbv = fmaf(-ALPHA, bbv, mc[m]);
            dst[m] = bbv;
            if (m == 1) b1v = bbv;
        }
        g_eb0[ch * TT + t] = expf(bbv);
        g_b1[ch * TT + t]  = b1v;
        if (tid == 0) g_f0[b * TT + t] = expf(fmaf(feat[45], 0.25f, 5.0f));
    }
}

// ==================================================================
// K2: pulse excitation — bit-exact replication of JAX associative_scan
// (odd/even recursive tree lowering of jnp.cumsum). Also zeroes d_out
// so k_mlsa can accumulate directly via atomics.
// ==================================================================
__global__ __launch_bounds__(256) void k_pulse(float* __restrict__ out)
{
    const int b   = blockIdx.x;
    const int tid = threadIdx.x;
    const int NTH = blockDim.x;

    // zero this batch's output span (poisoned by harness)
    for (int i = tid; i < NN; i += NTH)
        out[b * NN + i] = 0.f;

    const int ln[15] = {24000,12000,6000,3000,1500,750,375,187,93,46,23,11,5,2,1};
    int off[15];
    off[0] = 0;
    #pragma unroll
    for (int k = 1; k < 15; k++) off[k] = off[k-1] + ln[k-1];

    float* buf = g_scanbuf + b * SCAN_TOTAL;

    for (int i = tid; i < NN; i += NTH)
        buf[i] = g_f0[b * TT + i / HOP] / SRF;
    __syncthreads();

    for (int k = 0; k < 14; k++) {
        const float* src = buf + off[k];
        float*       dst = buf + off[k+1];
        const int nn1 = ln[k+1];
        for (int i = tid; i < nn1; i += NTH)
            dst[i] = src[2*i] + src[2*i+1];
        __syncthreads();
    }

    for (int k = 13; k >= 0; k--) {
        float*       a = buf + off[k];
        const float* s = buf + off[k+1];
        const int n = ln[k];
        for (int i = tid; i < n; i += NTH) {
            float v;
            if (i & 1)            v = s[i >> 1];
            else if (i == 0)      v = a[0];
            else                  v = s[(i >> 1) - 1] + a[i];
            a[i] = v;
        }
        __syncthreads();
    }

    for (int i = tid; i < NN; i += NTH) {
        float w  = floorf(buf[i]);
        float wp = (i == 0) ? 0.f : floorf(buf[i-1]);
        float f  = g_f0[b * TT + i / HOP];
        float amp = 0.5f * sqrtf(SRF / fmaxf(f, 1.0f));
        g_exc[b * NN + i] = (w > wp) ? amp : 0.f;
    }
}

// ==================================================================
// K3: MLSA synthesis filter scan — ONE WARP PER (channel, time-segment).
// Inner-loop body identical to the measured-good R7/R10/R12 kernel.
// Zero-state warm-up WARM samples before the write window, clamped to
// sample 0 (exact for early segments). Output accumulated directly into
// d_out via atomicAdd: exactly two commutative f32 adds per element
// (periodic + aperiodic channel) -> bitwise deterministic.
//   lanes 0..3 : stage-2 Pade tap p = lane (38-reg delay line)
//   all lanes  : stage-1 replicated; exchange via 4x shfl + shfl_up
// ==================================================================
__global__ __launch_bounds__(32, 1) void k_mlsa(const float* __restrict__ noise,
                                                float* __restrict__ out)
{
    const int blk  = blockIdx.x;          // 0..NCH*SEG-1
    const int c    = blk / SEG;           // channel
    const int s    = blk % SEG;           // time segment
    const int lane = threadIdx.x;         // taps on lanes 0..3

    const int wbeg = s * SEGLEN;                      // first written sample
    const int wend = wbeg + SEGLEN;
    int abeg = wbeg - WARM;                           // processing start
    if (abeg < 0) abeg = 0;                           // clamp (exact for early segs)
    const int fr0  = abeg / HOP;
    const int frw  = wbeg / HOP;
    const int fr1  = wend / HOP;

    // ---- stage-2 tap state ----
    float n[38];
    #pragma unroll
    for (int j = 0; j < 38; j++) n[j] = 0.f;
    float breg[38];
    float d1o = 0.f, xin = 0.f;

    // ---- stage-1 state (replicated on every lane) ----
    float x1p = 0.f, npt0 = 0.f, npt1 = 0.f, npt2 = 0.f;
    float na0 = 0.f, na1 = 0.f, na2 = 0.f, na3 = 0.f;

    const float* bc  = g_bcoef + c * TT * M1;
    const bool periodic = (c < 4);
    const float* src = periodic ? (g_exc + c * NN) : (noise + (c - 4) * NN);
    const float scl  = periodic ? 1.0f : 0.5f;
    float* oout = out + (c & 3) * NN;     // batch = c mod 4

    float excv = src[abeg] * scl;         // prefetch first sample

    for (int fr = fr0; fr < fr1; fr++) {
        const float* bf_ = bc + fr * M1;
        const float eb0 = g_eb0[c * TT + fr];
        const float b1  = g_b1[c * TT + fr];
        #pragma unroll
        for (int j = 0; j < 38; j++) breg[j] = bf_[2 + j];   // broadcast loads

        const bool wr = (fr >= frw);
        const int base = fr * HOP;

        for (int j = 0; j < HOP; j++) {
            const int i = base + j;

            // ---- stage-1 (mlsadf1), replicated on all lanes ----
            float x  = excv * eb0;
            float m0 = fmaf(ALPHA, na0, AAC * x1p);
            float m1 = fmaf(ALPHA, na1, AAC * npt0);
            float m2 = fmaf(ALPHA, na2, AAC * npt1);
            float m3 = fmaf(ALPHA, na3, AAC * npt2);
            na0 = m0; na1 = m1; na2 = m2; na3 = m3;
            float p0 = m0 * b1, p1 = m1 * b1, p2 = m2 * b1, p3 = m3 * b1;
            float sA1 = fmaf(P3C, p2, P1C * p0);
            float sB1 = fmaf(P4C, p3, P2C * p1);
            float x1 = x + (sA1 - sB1);
            float y1 = x1 + (sA1 + sB1);
            x1p = x1; npt0 = p0; npt1 = p1; npt2 = p2;

            // prefetch next excitation sample (off critical path)
            if (i + 1 < NN) excv = src[i + 1] * scl;

            // ---- stage-2 tap (mlsafir order recurrence), lane = tap ----
            float d1n = fmaf(ALPHA, d1o, AAC * xin);
            float pm1 = n[0];
            float nw  = fmaf(-ALPHA, d1n, fmaf(ALPHA, n[0], d1o));
            float y   = nw * breg[0];
            n[0] = nw;
            #pragma unroll
            for (int m = 1; m < 38; m++) {
                float cc = fmaf(ALPHA, n[m], pm1);   // off-chain
                pm1 = n[m];
                nw  = fmaf(-ALPHA, nw, cc);          // 4-cyc chain
                y   = fmaf(nw, breg[m], y);          // off-chain accum
                n[m] = nw;
            }
            d1o = d1n;

            // ---- cross-tap exchange + Pade reduce (all lanes, converged) ----
            float t0 = __shfl_sync(0xffffffffu, y, 0);
            float t1 = __shfl_sync(0xffffffffu, y, 1);
            float t2 = __shfl_sync(0xffffffffu, y, 2);
            float t3 = __shfl_sync(0xffffffffu, y, 3);
            float sA = fmaf(P3C, t2, P1C * t0);
            float sB = fmaf(P4C, t3, P2C * t1);
            float x2 = y1 + (sA - sB);
            float y2 = x2 + (sA + sB);
            if (lane == 0 && wr) atomicAdd(&oout[i], y2);   // REDG, off-path

            // next-sample tap inputs: pt2 = [x2, fy0, fy1, fy2]
            float up = __shfl_up_sync(0xffffffffu, y, 1);
            xin = (lane == 0) ? x2 : up;
        }
    }
}

// ==================================================================
extern "C" void kernel_launch(void* const* d_in, const int* in_sizes, int n_in,
                              void* d_out, int out_size)
{
    const float* mceps = (const float*)d_in[0];
    const float* apdcs = (const float*)d_in[1];
    const float* f0s   = (const float*)d_in[2];
    const float* noise = (const float*)d_in[3];
    const float* Wm  = (const float*)d_in[4];
    const float* bm  = (const float*)d_in[5];
    const float* Wa  = (const float*)d_in[6];
    const float* ba  = (const float*)d_in[7];
    const float* Wf  = (const float*)d_in[8];
    const float* bf  = (const float*)d_in[9];
    const float* Wpa = (const float*)d_in[10];
    const float* bpa = (const float*)d_in[11];
    const float* Wpp = (const float*)d_in[12];
    const float* bpp = (const float*)d_in[13];
    const float* Wrp = (const float*)d_in[14];
    const float* brp = (const float*)d_in[15];
    const float* Wra = (const float*)d_in[16];
    const float* bra = (const float*)d_in[17];
    const float* Wap = (const float*)d_in[18];

    k_frontend<<<BB * TT, 256>>>(mceps, apdcs, f0s,
                                 Wm, bm, Wa, ba, Wf, bf,
                                 Wpa, bpa, Wpp, bpp,
                                 Wrp, brp, Wra, bra, Wap);
    k_pulse<<<BB, 256>>>((float*)d_out);
    k_mlsa<<<NCH * SEG, 32>>>(noise, (float*)d_out);
}

// round 15
// speedup vs baseline: 28.5761x; 1.2947x over previous
#include <cuda_runtime.h>
#include <math.h>

// ---------------- problem constants ----------------
#define BB    4
#define TT    200
#define HOP   120
#define NN    24000          // T*HOP
#define M1    40
#define A1    5
#define HID   256
#define COND  192
#define NCH   8              // 2B channels (0..3 periodic, 4..7 aperiodic)

#define ALPHA 0.466f
#define AAC   0.782844f      // 1 - ALPHA^2
#define P1C   0.4999273f
#define P2C   0.1067005f
#define P3C   0.00956526f
#define P4C   0.0003041358f
#define SRF   24000.0f

// time-segmentation of the MLSA scan
// Measured transients: ~1e-8 @1200, ~1.3e-8 @720 => rate ~0.025/sample
// => WARM=480 residual ~5e-6 << 1e-3.
#define SEG     100          // segments per channel (2 frames each)
#define SEGLEN  240          // NN / SEG
#define WARM    480          // warm-up samples (4 frames), zero-state start

#define TB 8                 // frames per frontend block

// ---------------- scratch (no allocations allowed) ----------------
__device__ float g_bcoef[NCH * TT * M1];   // MLSA coefficients per channel/frame
__device__ float g_eb0[NCH * TT];          // exp(b[0]) per channel/frame
__device__ float g_b1[NCH * TT];           // b[1] per channel/frame
__device__ float g_f0[BB * TT];            // denormed f0 per batch/frame
__device__ float g_exc[BB * NN];           // periodic excitation (0.5 * pulse)
// tree-scan levels: 24000,12000,6000,3000,1500,750,375,187,93,46,23,11,5,2,1
#define SCAN_TOTAL 47993
__device__ float g_scanbuf[BB * SCAN_TOTAL];

// ==================================================================
// K1: dense frontend, tiled TB=8 frames per block: every weight load
// is reused across 8 frames (smem-staged activations). Per-output
// scalar accumulation order identical to the previous (passing) kernel.
// grid = BB * (TT/TB) = 100 blocks x 256 threads.
// ==================================================================
__global__ __launch_bounds__(256) void k_frontend(
    const float* __restrict__ mceps, const float* __restrict__ apdcs,
    const float* __restrict__ f0s,
    const float* __restrict__ Wm,  const float* __restrict__ bm,
    const float* __restrict__ Wa,  const float* __restrict__ ba,
    const float* __restrict__ Wf,  const float* __restrict__ bf,
    const float* __restrict__ Wpa, const float* __restrict__ bpa,
    const float* __restrict__ Wpp, const float* __restrict__ bpp,
    const float* __restrict__ Wrp, const float* __restrict__ brp,
    const float* __restrict__ Wra, const float* __restrict__ bra,
    const float* __restrict__ Wap)
{
    const int blk = blockIdx.x;             // 0..99
    const int b   = blk / (TT / TB);        // batch
    const int t0  = (blk % (TT / TB)) * TB; // first frame of tile
    const int tid = threadIdx.x;

    __shared__ float feat[TB][48];          // mcep[40] | apdc[5] | f0
    __shared__ float hsm [TB][HID + 1];
    __shared__ float caa [TB][COND + 1];
    __shared__ float cpp [TB][COND + 1];
    __shared__ float mcp [TB][M1 + 1];
    __shared__ float mca [TB][M1 + 1];

    // ---- load features for 8 frames ----
    for (int idx = tid; idx < TB * 46; idx += 256) {
        int f = idx / 46, j = idx % 46;
        int bt = b * TT + t0 + f;
        float v;
        if (j < M1)       v = mceps[bt * M1 + j];
        else if (j < 45)  v = apdcs[bt * A1 + (j - M1)];
        else              v = f0s[bt];
        feat[f][j] = v;
    }
    __syncthreads();

    // ---- stage 1: hs = mceps@Wm + bm + apdcs@Wa + ba + f0@Wf + bf ----
    {
        float base = bm[tid] + ba[tid] + bf[tid];
        float acc[TB];
        #pragma unroll
        for (int f = 0; f < TB; f++) acc[f] = base;
        for (int i = 0; i < M1; i++) {
            float w = Wm[i * HID + tid];
            #pragma unroll
            for (int f = 0; f < TB; f++) acc[f] = fmaf(feat[f][i], w, acc[f]);
        }
        #pragma unroll
        for (int i = 0; i < A1; i++) {
            float w = Wa[i * HID + tid];
            #pragma unroll
            for (int f = 0; f < TB; f++) acc[f] = fmaf(feat[f][M1 + i], w, acc[f]);
        }
        float wf = Wf[tid];
        #pragma unroll
        for (int f = 0; f < TB; f++) {
            acc[f] = fmaf(feat[f][45], wf, acc[f]);
            hsm[f][tid] = acc[f];
        }
    }
    __syncthreads();

    // ---- stage 2: cond projections (COND threads, 16 accumulators) ----
    if (tid < COND) {
        float sa[TB], sp[TB];
        float b_a = bpa[tid], b_p = bpp[tid];
        #pragma unroll
        for (int f = 0; f < TB; f++) { sa[f] = b_a; sp[f] = b_p; }
        #pragma unroll 2
        for (int i = 0; i < HID; i++) {
            float wa = Wpa[i * COND + tid];
            float wp = Wpp[i * COND + tid];
            #pragma unroll
            for (int f = 0; f < TB; f++) {
                float h = hsm[f][i];
                sa[f] = fmaf(h, wa, sa[f]);
                sp[f] = fmaf(h, wp, sp[f]);
            }
        }
        #pragma unroll
        for (int f = 0; f < TB; f++) { caa[f][tid] = sa[f]; cpp[f][tid] = sp[f]; }
    }
    __syncthreads();

    // ---- stage 3: residual projections + Wap ----
    if (tid < M1) {
        float rp[TB], ra[TB];
        float b_rp = brp[tid], b_ra = bra[tid];
        #pragma unroll
        for (int f = 0; f < TB; f++) { rp[f] = b_rp; ra[f] = b_ra; }
        #pragma unroll 2
        for (int i = 0; i < COND; i++) {
            float wrp = Wrp[i * M1 + tid];
            float wra = Wra[i * M1 + tid];
            #pragma unroll
            for (int f = 0; f < TB; f++) {
                rp[f] = fmaf(cpp[f][i], wrp, rp[f]);
                ra[f] = fmaf(caa[f][i], wra, ra[f]);
            }
        }
        float apm[TB];
        #pragma unroll
        for (int f = 0; f < TB; f++) apm[f] = 0.f;
        #pragma unroll
        for (int i = 0; i < A1; i++) {
            float w = Wap[i * M1 + tid];
            #pragma unroll
            for (int f = 0; f < TB; f++) apm[f] = fmaf(feat[f][M1 + i], w, apm[f]);
        }
        #pragma unroll
        for (int f = 0; f < TB; f++) {
            float sp_ = feat[f][tid];
            mcp[f][tid] = sp_ + 0.1f * tanhf(rp[f]);
            mca[f][tid] = sp_ + 0.1f * tanhf(ra[f]) + apm[f];
        }
    }
    __syncthreads();

    // ---- mc2b (serial order scan), one thread per (frame, path) ----
    if (tid < 2 * TB) {
        int f    = tid >> 1;
        int path = tid & 1;
        const float* mc = (path == 0) ? mcp[f] : mca[f];
        int ch = (path == 0) ? b : (4 + b);
        int t  = t0 + f;
        float* dst = g_bcoef + (ch * TT + t) * M1;
        float bbv = 0.f, b1v = 0.f;
        #pragma unroll
        for (int m = M1 - 1; m >= 0; m--) {
            bbv = fmaf(-ALPHA, bbv, mc[m]);
            dst[m] = bbv;
            if (m == 1) b1v = bbv;
        }
        g_eb0[ch * TT + t] = expf(bbv);
        g_b1[ch * TT + t]  = b1v;
        if (path == 0) g_f0[b * TT + t] = expf(fmaf(feat[f][45], 0.25f, 5.0f));
    }
}

// ==================================================================
// K2: pulse excitation — bit-exact replication of JAX associative_scan
// (odd/even recursive tree lowering of jnp.cumsum). Also zeroes d_out
// so k_mlsa can accumulate directly via atomics. 1024 threads.
// ==================================================================
__global__ __launch_bounds__(1024) void k_pulse(float* __restrict__ out)
{
    const int b   = blockIdx.x;
    const int tid = threadIdx.x;
    const int NTH = 1024;

    // zero this batch's output span (poisoned by harness)
    for (int i = tid; i < NN; i += NTH)
        out[b * NN + i] = 0.f;

    const int ln[15] = {24000,12000,6000,3000,1500,750,375,187,93,46,23,11,5,2,1};
    int off[15];
    off[0] = 0;
    #pragma unroll
    for (int k = 1; k < 15; k++) off[k] = off[k-1] + ln[k-1];

    float* buf = g_scanbuf + b * SCAN_TOTAL;

    for (int i = tid; i < NN; i += NTH)
        buf[i] = g_f0[b * TT + i / HOP] / SRF;
    __syncthreads();

    for (int k = 0; k < 14; k++) {
        const float* src = buf + off[k];
        float*       dst = buf + off[k+1];
        const int nn1 = ln[k+1];
        for (int i = tid; i < nn1; i += NTH)
            dst[i] = src[2*i] + src[2*i+1];
        __syncthreads();
    }

    for (int k = 13; k >= 0; k--) {
        float*       a = buf + off[k];
        const float* s = buf + off[k+1];
        const int n = ln[k];
        for (int i = tid; i < n; i += NTH) {
            float v;
            if (i & 1)            v = s[i >> 1];
            else if (i == 0)      v = a[0];
            else                  v = s[(i >> 1) - 1] + a[i];
            a[i] = v;
        }
        __syncthreads();
    }

    for (int i = tid; i < NN; i += NTH) {
        float w  = floorf(buf[i]);
        float wp = (i == 0) ? 0.f : floorf(buf[i-1]);
        float f  = g_f0[b * TT + i / HOP];
        float amp = 0.5f * sqrtf(SRF / fmaxf(f, 1.0f));
        g_exc[b * NN + i] = (w > wp) ? amp : 0.f;
    }
}

// ==================================================================
// K3: MLSA synthesis filter scan — ONE WARP PER (channel, time-segment).
// Inner-loop body identical to the measured-good R7/R10/R12/R13 kernel.
// Zero-state warm-up WARM samples before the write window, clamped to
// sample 0 (exact for early segments). Output accumulated directly into
// d_out via atomicAdd (two commutative adds/element -> deterministic).
// ==================================================================
__global__ __launch_bounds__(32, 1) void k_mlsa(const float* __restrict__ noise,
                                                float* __restrict__ out)
{
    const int blk  = blockIdx.x;          // 0..NCH*SEG-1
    const int c    = blk / SEG;           // channel
    const int s    = blk % SEG;           // time segment
    const int lane = threadIdx.x;         // taps on lanes 0..3

    const int wbeg = s * SEGLEN;                      // first written sample
    const int wend = wbeg + SEGLEN;
    int abeg = wbeg - WARM;                           // processing start
    if (abeg < 0) abeg = 0;                           // clamp (exact for early segs)
    const int fr0  = abeg / HOP;
    const int frw  = wbeg / HOP;
    const int fr1  = wend / HOP;

    // ---- stage-2 tap state ----
    float n[38];
    #pragma unroll
    for (int j = 0; j < 38; j++) n[j] = 0.f;
    float breg[38];
    float d1o = 0.f, xin = 0.f;

    // ---- stage-1 state (replicated on every lane) ----
    float x1p = 0.f, npt0 = 0.f, npt1 = 0.f, npt2 = 0.f;
    float na0 = 0.f, na1 = 0.f, na2 = 0.f, na3 = 0.f;

    const float* bc  = g_bcoef + c * TT * M1;
    const bool periodic = (c < 4);
    const float* src = periodic ? (g_exc + c * NN) : (noise + (c - 4) * NN);
    const float scl  = periodic ? 1.0f : 0.5f;
    float* oout = out + (c & 3) * NN;     // batch = c mod 4

    float excv = src[abeg] * scl;         // prefetch first sample

    for (int fr = fr0; fr < fr1; fr++) {
        const float* bf_ = bc + fr * M1;
        const float eb0 = g_eb0[c * TT + fr];
        const float b1  = g_b1[c * TT + fr];
        #pragma unroll
        for (int j = 0; j < 38; j++) breg[j] = bf_[2 + j];   // broadcast loads

        const bool wr = (fr >= frw);
        const int base = fr * HOP;

        for (int j = 0; j < HOP; j++) {
            const int i = base + j;

            // ---- stage-1 (mlsadf1), replicated on all lanes ----
            float x  = excv * eb0;
            float m0 = fmaf(ALPHA, na0, AAC * x1p);
            float m1 = fmaf(ALPHA, na1, AAC * npt0);
            float m2 = fmaf(ALPHA, na2, AAC * npt1);
            float m3 = fmaf(ALPHA, na3, AAC * npt2);
            na0 = m0; na1 = m1; na2 = m2; na3 = m3;
            float p0 = m0 * b1, p1 = m1 * b1, p2 = m2 * b1, p3 = m3 * b1;
            float sA1 = fmaf(P3C, p2, P1C * p0);
            float sB1 = fmaf(P4C, p3, P2C * p1);
            float x1 = x + (sA1 - sB1);
            float y1 = x1 + (sA1 + sB1);
            x1p = x1; npt0 = p0; npt1 = p1; npt2 = p2;

            // prefetch next excitation sample (off critical path)
            if (i + 1 < NN) excv = src[i + 1] * scl;

            // ---- stage-2 tap (mlsafir order recurrence), lane = tap ----
            float d1n = fmaf(ALPHA, d1o, AAC * xin);
            float pm1 = n[0];
            float nw  = fmaf(-ALPHA, d1n, fmaf(ALPHA, n[0], d1o));
            float y   = nw * breg[0];
            n[0] = nw;
            #pragma unroll
            for (int m = 1; m < 38; m++) {
                float cc = fmaf(ALPHA, n[m], pm1);   // off-chain
                pm1 = n[m];
                nw  = fmaf(-ALPHA, nw, cc);          // 4-cyc chain
                y   = fmaf(nw, breg[m], y);          // off-chain accum
                n[m] = nw;
            }
            d1o = d1n;

            // ---- cross-tap exchange + Pade reduce (all lanes, converged) ----
            float t0 = __shfl_sync(0xffffffffu, y, 0);
            float t1 = __shfl_sync(0xffffffffu, y, 1);
            float t2 = __shfl_sync(0xffffffffu, y, 2);
            float t3 = __shfl_sync(0xffffffffu, y, 3);
            float sA = fmaf(P3C, t2, P1C * t0);
            float sB = fmaf(P4C, t3, P2C * t1);
            float x2 = y1 + (sA - sB);
            float y2 = x2 + (sA + sB);
            if (lane == 0 && wr) atomicAdd(&oout[i], y2);   // REDG, off-path

            // next-sample tap inputs: pt2 = [x2, fy0, fy1, fy2]
            float up = __shfl_up_sync(0xffffffffu, y, 1);
            xin = (lane == 0) ? x2 : up;
        }
    }
}

// ==================================================================
extern "C" void kernel_launch(void* const* d_in, const int* in_sizes, int n_in,
                              void* d_out, int out_size)
{
    const float* mceps = (const float*)d_in[0];
    const float* apdcs = (const float*)d_in[1];
    const float* f0s   = (const float*)d_in[2];
    const float* noise = (const float*)d_in[3];
    const float* Wm  = (const float*)d_in[4];
    const float* bm  = (const float*)d_in[5];
    const float* Wa  = (const float*)d_in[6];
    const float* ba  = (const float*)d_in[7];
    const float* Wf  = (const float*)d_in[8];
    const float* bf  = (const float*)d_in[9];
    const float* Wpa = (const float*)d_in[10];
    const float* bpa = (const float*)d_in[11];
    const float* Wpp = (const float*)d_in[12];
    const float* bpp = (const float*)d_in[13];
    const float* Wrp = (const float*)d_in[14];
    const float* brp = (const float*)d_in[15];
    const float* Wra = (const float*)d_in[16];
    const float* bra = (const float*)d_in[17];
    const float* Wap = (const float*)d_in[18];

    k_frontend<<<BB * (TT / TB), 256>>>(mceps, apdcs, f0s,
                                        Wm, bm, Wa, ba, Wf, bf,
                                        Wpa, bpa, Wpp, bpp,
                                        Wrp, brp, Wra, bra, Wap);
    k_pulse<<<BB, 1024>>>((float*)d_out);
    k_mlsa<<<NCH * SEG, 32>>>(noise, (float*)d_out);
}

// round 16
// speedup vs baseline: 33.8050x; 1.1830x over previous
#include <cuda_runtime.h>
#include <math.h>

// ---------------- problem constants ----------------
#define BB    4
#define TT    200
#define HOP   120
#define NN    24000          // T*HOP
#define M1    40
#define A1    5
#define HID   256
#define COND  192
#define NCH   8              // 2B channels (0..3 periodic, 4..7 aperiodic)

#define ALPHA 0.466f
#define AAC   0.782844f      // 1 - ALPHA^2
#define P1C   0.4999273f
#define P2C   0.1067005f
#define P3C   0.00956526f
#define P4C   0.0003041358f
#define SRF   24000.0f

// time-segmentation: 1 write frame per group, 3 zero-state warm frames.
// Measured transients: 1.4e-8 @720, 8.4e-8 @480 => rate ~0.0075/sample
// => WARM=360 residual ~2e-7 (25x model error still leaves 5e-6 << 1e-3).
// Early segments (s<3) are EXACT: zero-feed of pre-history == true zero
// initial state for a linear filter.
#define SEG    200           // segments per channel = frames
#define WARMF  3             // warm-up frames
#define TB 8                 // frames per frontend block

// ---------------- scratch (no allocations allowed) ----------------
__device__ float g_bcoef[NCH * TT * M1];   // MLSA coefficients per channel/frame
__device__ float g_eb0[NCH * TT];          // exp(b[0]) per channel/frame
__device__ float g_b1[NCH * TT];           // b[1] per channel/frame
__device__ float g_f0[BB * TT];            // denormed f0 per batch/frame
__device__ float g_exc[BB * NN];           // periodic excitation (0.5 * pulse)
// tree-scan levels: 24000,12000,6000,3000,1500,750,375,187,93,46,23,11,5,2,1
#define SCAN_TOTAL 47993
__device__ float g_scanbuf[BB * SCAN_TOTAL];

// ==================================================================
// K1: dense frontend, tiled TB=8 frames per block (unchanged from the
// 236us-passing kernel).
// ==================================================================
__global__ __launch_bounds__(256) void k_frontend(
    const float* __restrict__ mceps, const float* __restrict__ apdcs,
    const float* __restrict__ f0s,
    const float* __restrict__ Wm,  const float* __restrict__ bm,
    const float* __restrict__ Wa,  const float* __restrict__ ba,
    const float* __restrict__ Wf,  const float* __restrict__ bf,
    const float* __restrict__ Wpa, const float* __restrict__ bpa,
    const float* __restrict__ Wpp, const float* __restrict__ bpp,
    const float* __restrict__ Wrp, const float* __restrict__ brp,
    const float* __restrict__ Wra, const float* __restrict__ bra,
    const float* __restrict__ Wap)
{
    const int blk = blockIdx.x;             // 0..99
    const int b   = blk / (TT / TB);        // batch
    const int t0  = (blk % (TT / TB)) * TB; // first frame of tile
    const int tid = threadIdx.x;

    __shared__ float feat[TB][48];          // mcep[40] | apdc[5] | f0
    __shared__ float hsm [TB][HID + 1];
    __shared__ float caa [TB][COND + 1];
    __shared__ float cpp [TB][COND + 1];
    __shared__ float mcp [TB][M1 + 1];
    __shared__ float mca [TB][M1 + 1];

    for (int idx = tid; idx < TB * 46; idx += 256) {
        int f = idx / 46, j = idx % 46;
        int bt = b * TT + t0 + f;
        float v;
        if (j < M1)       v = mceps[bt * M1 + j];
        else if (j < 45)  v = apdcs[bt * A1 + (j - M1)];
        else              v = f0s[bt];
        feat[f][j] = v;
    }
    __syncthreads();

    {
        float base = bm[tid] + ba[tid] + bf[tid];
        float acc[TB];
        #pragma unroll
        for (int f = 0; f < TB; f++) acc[f] = base;
        for (int i = 0; i < M1; i++) {
            float w = Wm[i * HID + tid];
            #pragma unroll
            for (int f = 0; f < TB; f++) acc[f] = fmaf(feat[f][i], w, acc[f]);
        }
        #pragma unroll
        for (int i = 0; i < A1; i++) {
            float w = Wa[i * HID + tid];
            #pragma unroll
            for (int f = 0; f < TB; f++) acc[f] = fmaf(feat[f][M1 + i], w, acc[f]);
        }
        float wf = Wf[tid];
        #pragma unroll
        for (int f = 0; f < TB; f++) {
            acc[f] = fmaf(feat[f][45], wf, acc[f]);
            hsm[f][tid] = acc[f];
        }
    }
    __syncthreads();

    if (tid < COND) {
        float sa[TB], sp[TB];
        float b_a = bpa[tid], b_p = bpp[tid];
        #pragma unroll
        for (int f = 0; f < TB; f++) { sa[f] = b_a; sp[f] = b_p; }
        #pragma unroll 2
        for (int i = 0; i < HID; i++) {
            float wa = Wpa[i * COND + tid];
            float wp = Wpp[i * COND + tid];
            #pragma unroll
            for (int f = 0; f < TB; f++) {
                float h = hsm[f][i];
                sa[f] = fmaf(h, wa, sa[f]);
                sp[f] = fmaf(h, wp, sp[f]);
            }
        }
        #pragma unroll
        for (int f = 0; f < TB; f++) { caa[f][tid] = sa[f]; cpp[f][tid] = sp[f]; }
    }
    __syncthreads();

    if (tid < M1) {
        float rp[TB], ra[TB];
        float b_rp = brp[tid], b_ra = bra[tid];
        #pragma unroll
        for (int f = 0; f < TB; f++) { rp[f] = b_rp; ra[f] = b_ra; }
        #pragma unroll 2
        for (int i = 0; i < COND; i++) {
            float wrp = Wrp[i * M1 + tid];
            float wra = Wra[i * M1 + tid];
            #pragma unroll
            for (int f = 0; f < TB; f++) {
                rp[f] = fmaf(cpp[f][i], wrp, rp[f]);
                ra[f] = fmaf(caa[f][i], wra, ra[f]);
            }
        }
        float apm[TB];
        #pragma unroll
        for (int f = 0; f < TB; f++) apm[f] = 0.f;
        #pragma unroll
        for (int i = 0; i < A1; i++) {
            float w = Wap[i * M1 + tid];
            #pragma unroll
            for (int f = 0; f < TB; f++) apm[f] = fmaf(feat[f][M1 + i], w, apm[f]);
        }
        #pragma unroll
        for (int f = 0; f < TB; f++) {
            float sp_ = feat[f][tid];
            mcp[f][tid] = sp_ + 0.1f * tanhf(rp[f]);
            mca[f][tid] = sp_ + 0.1f * tanhf(ra[f]) + apm[f];
        }
    }
    __syncthreads();

    if (tid < 2 * TB) {
        int f    = tid >> 1;
        int path = tid & 1;
        const float* mc = (path == 0) ? mcp[f] : mca[f];
        int ch = (path == 0) ? b : (4 + b);
        int t  = t0 + f;
        float* dst = g_bcoef + (ch * TT + t) * M1;
        float bbv = 0.f, b1v = 0.f;
        #pragma unroll
        for (int m = M1 - 1; m >= 0; m--) {
            bbv = fmaf(-ALPHA, bbv, mc[m]);
            dst[m] = bbv;
            if (m == 1) b1v = bbv;
        }
        g_eb0[ch * TT + t] = expf(bbv);
        g_b1[ch * TT + t]  = b1v;
        if (path == 0) g_f0[b * TT + t] = expf(fmaf(feat[f][45], 0.25f, 5.0f));
    }
}

// ==================================================================
// K2: pulse excitation — bit-exact JAX associative_scan tree. Zeroes d_out.
// ==================================================================
__global__ __launch_bounds__(1024) void k_pulse(float* __restrict__ out)
{
    const int b   = blockIdx.x;
    const int tid = threadIdx.x;
    const int NTH = 1024;

    for (int i = tid; i < NN; i += NTH)
        out[b * NN + i] = 0.f;

    const int ln[15] = {24000,12000,6000,3000,1500,750,375,187,93,46,23,11,5,2,1};
    int off[15];
    off[0] = 0;
    #pragma unroll
    for (int k = 1; k < 15; k++) off[k] = off[k-1] + ln[k-1];

    float* buf = g_scanbuf + b * SCAN_TOTAL;

    for (int i = tid; i < NN; i += NTH)
        buf[i] = g_f0[b * TT + i / HOP] / SRF;
    __syncthreads();

    for (int k = 0; k < 14; k++) {
        const float* src = buf + off[k];
        float*       dst = buf + off[k+1];
        const int nn1 = ln[k+1];
        for (int i = tid; i < nn1; i += NTH)
            dst[i] = src[2*i] + src[2*i+1];
        __syncthreads();
    }

    for (int k = 13; k >= 0; k--) {
        float*       a = buf + off[k];
        const float* s = buf + off[k+1];
        const int n = ln[k];
        for (int i = tid; i < n; i += NTH) {
            float v;
            if (i & 1)            v = s[i >> 1];
            else if (i == 0)      v = a[0];
            else                  v = s[(i >> 1) - 1] + a[i];
            a[i] = v;
        }
        __syncthreads();
    }

    for (int i = tid; i < NN; i += NTH) {
        float w  = floorf(buf[i]);
        float wp = (i == 0) ? 0.f : floorf(buf[i-1]);
        float f  = g_f0[b * TT + i / HOP];
        float amp = 0.5f * sqrtf(SRF / fmaxf(f, 1.0f));
        g_exc[b * NN + i] = (w > wp) ? amp : 0.f;
    }
}

// ==================================================================
// K3: MLSA synthesis — EIGHT (channel,frame) groups PER WARP.
// Each 4-lane group runs the measured-good tap structure (tap = lane&3,
// stage-1 replicated in-group, group-local shfl exchange). One shared
// instruction stream amortizes the ~190 issue-slots/sample across 8
// groups; 200 one-warp blocks => every warp on its own SMSP =>
// latency-bound at ~330 cyc/sample x 480 samples.
// Uniform 4-frame loop: 3 warm frames + 1 write frame. Frames before
// t=0 are zero-fed (exact: zero state + zero input stays zero), with
// coefficient pointers clamped to frame 0.
// ==================================================================
__global__ __launch_bounds__(32, 1) void k_mlsa(const float* __restrict__ noise,
                                                float* __restrict__ out)
{
    const int lane = threadIdx.x;
    const int gid  = blockIdx.x * 8 + (lane >> 2);  // group 0..1599
    const int sub  = lane & 3;                      // tap within group
    const int gb   = lane & 28;                     // group base lane
    const int c    = gid / SEG;                     // channel
    const int s    = gid % SEG;                     // write frame

    // ---- stage-2 tap state ----
    float n[38];
    #pragma unroll
    for (int j = 0; j < 38; j++) n[j] = 0.f;
    float breg[38];
    float d1o = 0.f, xin = 0.f;

    // ---- stage-1 state (replicated within each group) ----
    float x1p = 0.f, npt0 = 0.f, npt1 = 0.f, npt2 = 0.f;
    float na0 = 0.f, na1 = 0.f, na2 = 0.f, na3 = 0.f;

    const float* bc  = g_bcoef + c * TT * M1;
    const bool periodic = (c < 4);
    const float* src = periodic ? (g_exc + c * NN) : (noise + (c - 4) * NN);
    const float sclc = periodic ? 1.0f : 0.5f;
    float* oout = out + (c & 3) * NN;               // batch = c mod 4

    #pragma unroll 1
    for (int k = 0; k <= WARMF; k++) {
        const int fr  = s - WARMF + k;              // may be negative
        const int frc = (fr < 0) ? 0 : fr;          // clamped frame
        const float esc = (fr < 0) ? 0.f : sclc;    // zero-feed pre-history
        const float* bf_ = bc + frc * M1;
        const float eb0 = g_eb0[c * TT + frc];
        const float b1  = g_b1[c * TT + frc];
        #pragma unroll
        for (int j = 0; j < 38; j++) breg[j] = bf_[2 + j];

        const bool wr = (k == WARMF);
        const int base = frc * HOP;
        float excv = src[base] * esc;

        for (int j = 0; j < HOP; j++) {
            // ---- stage-1 (mlsadf1), replicated within group ----
            float x  = excv * eb0;
            float m0 = fmaf(ALPHA, na0, AAC * x1p);
            float m1 = fmaf(ALPHA, na1, AAC * npt0);
            float m2 = fmaf(ALPHA, na2, AAC * npt1);
            float m3 = fmaf(ALPHA, na3, AAC * npt2);
            na0 = m0; na1 = m1; na2 = m2; na3 = m3;
            float p0 = m0 * b1, p1 = m1 * b1, p2 = m2 * b1, p3 = m3 * b1;
            float sA1 = fmaf(P3C, p2, P1C * p0);
            float sB1 = fmaf(P4C, p3, P2C * p1);
            float x1 = x + (sA1 - sB1);
            float y1 = x1 + (sA1 + sB1);
            x1p = x1; npt0 = p0; npt1 = p1; npt2 = p2;

            // prefetch next excitation sample (off critical path)
            if (j + 1 < HOP) excv = src[base + j + 1] * esc;

            // ---- stage-2 tap (mlsafir order recurrence), tap = sub ----
            float d1n = fmaf(ALPHA, d1o, AAC * xin);
            float pm1 = n[0];
            float nw  = fmaf(-ALPHA, d1n, fmaf(ALPHA, n[0], d1o));
            float y   = nw * breg[0];
            n[0] = nw;
            #pragma unroll
            for (int m = 1; m < 38; m++) {
                float cc = fmaf(ALPHA, n[m], pm1);   // off-chain
                pm1 = n[m];
                nw  = fmaf(-ALPHA, nw, cc);          // 4-cyc chain
                y   = fmaf(nw, breg[m], y);          // off-chain accum
                n[m] = nw;
            }
            d1o = d1n;

            // ---- group-local exchange + Pade reduce ----
            float t0 = __shfl_sync(0xffffffffu, y, gb + 0);
            float t1 = __shfl_sync(0xffffffffu, y, gb + 1);
            float t2 = __shfl_sync(0xffffffffu, y, gb + 2);
            float t3 = __shfl_sync(0xffffffffu, y, gb + 3);
            float sA = fmaf(P3C, t2, P1C * t0);
            float sB = fmaf(P4C, t3, P2C * t1);
            float x2 = y1 + (sA - sB);
            float y2 = x2 + (sA + sB);
            if (sub == 0 && wr) atomicAdd(&oout[base + j], y2);  // REDG

            // next-sample tap inputs: [x2, fy0, fy1, fy2]
            xin = (sub == 0) ? x2
                : (sub == 1) ? t0
                : (sub == 2) ? t1
                : t2;
        }
    }
}

// ==================================================================
extern "C" void kernel_launch(void* const* d_in, const int* in_sizes, int n_in,
                              void* d_out, int out_size)
{
    const float* mceps = (const float*)d_in[0];
    const float* apdcs = (const float*)d_in[1];
    const float* f0s   = (const float*)d_in[2];
    const float* noise = (const float*)d_in[3];
    const float* Wm  = (const float*)d_in[4];
    const float* bm  = (const float*)d_in[5];
    const float* Wa  = (const float*)d_in[6];
    const float* ba  = (const float*)d_in[7];
    const float* Wf  = (const float*)d_in[8];
    const float* bf  = (const float*)d_in[9];
    const float* Wpa = (const float*)d_in[10];
    const float* bpa = (const float*)d_in[11];
    const float* Wpp = (const float*)d_in[12];
    const float* bpp = (const float*)d_in[13];
    const float* Wrp = (const float*)d_in[14];
    const float* brp = (const float*)d_in[15];
    const float* Wra = (const float*)d_in[16];
    const float* bra = (const float*)d_in[17];
    const float* Wap = (const float*)d_in[18];

    k_frontend<<<BB * (TT / TB), 256>>>(mceps, apdcs, f0s,
                                        Wm, bm, Wa, ba, Wf, bf,
                                        Wpa, bpa, Wpp, bpp,
                                        Wrp, brp, Wra, bra, Wap);
    k_pulse<<<BB, 1024>>>((float*)d_out);
    k_mlsa<<<(NCH * SEG) / 8, 32>>>(noise, (float*)d_out);
}